// round 1
// baseline (speedup 1.0000x reference)
#include <cuda_runtime.h>
#include <math.h>

#define NN   512
#define FIN  256
#define HF   64
#define KTOP 12
#define LALPHA 0.2f
#define RMAX 16     // hard upper bound: strict > kth(12th) gives <= 11 nonzeros

// ---------------- scratch (__device__ globals; no allocation) ----------------
__device__ float g_A[NN * NN];            // V @ V^T
__device__ float g_kth;
__device__ int   g_rowCnt[NN];
__device__ int   g_cols[NN][RMAX];        // adjacency columns per row
__device__ int   g_nRows;
__device__ int   g_rowIds[RMAX];
__device__ int   g_rIndexOf[NN];          // node -> slot in R, or -1
__device__ int   g_nD;
__device__ int   g_dCols[RMAX];           // distinct adjacency columns
__device__ int   g_dIndexOf[NN];
__device__ float g_w1[NN * FIN];          // W_h @ a1_h
__device__ float g_w2[NN * FIN];          // W_h @ a2_h
__device__ float g_e2[NN * NN];           // e2[h][j] = X[j] . w2[h]
__device__ float g_e1R[RMAX * NN];        // e1 for rows in R: [slot][h]
__device__ float g_WhC[NN * RMAX * HF];   // Wh[h][distinct col jd][c]
__device__ float g_midR[RMAX * NN * HF];  // nonzero rows of mid (16 x 32768)
__device__ float g_part[256 * RMAX * HF]; // Wh2 partials (deterministic reduce)
__device__ float g_Wh2[RMAX * HF];
__device__ float g_e12[RMAX];
__device__ float g_e22[RMAX];

__device__ __forceinline__ float lrelu(float x) { return x > 0.f ? x : LALPHA * x; }
__device__ __forceinline__ float eluf(float x)  { return x > 0.f ? x : expm1f(x); }

// ---------------- 1) A = V @ V^T ----------------
__global__ void k_vvt(const float* __restrict__ V) {
    __shared__ float sVi[HF];
    int i = blockIdx.x, tid = threadIdx.x;
    if (tid < HF) sVi[tid] = V[i * HF + tid];
    __syncthreads();
    float acc = 0.f;
    const float* Vj = V + tid * HF;
#pragma unroll
    for (int k = 0; k < HF; k++) acc += sVi[k] * Vj[k];
    g_A[i * NN + tid] = acc;
}

// ---------------- 2) 12th largest of g_A ----------------
__global__ void k_topk() {
    __shared__ float s[256 * KTOP];
    __shared__ float rv[256];
    __shared__ int   ri[256];
    int tid = threadIdx.x;
    float loc[KTOP];
#pragma unroll
    for (int k = 0; k < KTOP; k++) loc[k] = -3.4e38f;   // ascending, loc[0] = min
    for (int idx = tid; idx < NN * NN; idx += 256) {
        float v = g_A[idx];
        if (v > loc[0]) {
            loc[0] = v;
#pragma unroll
            for (int k = 0; k < KTOP - 1; k++) {
                if (loc[k] > loc[k + 1]) { float t = loc[k]; loc[k] = loc[k + 1]; loc[k + 1] = t; }
            }
        }
    }
#pragma unroll
    for (int k = 0; k < KTOP; k++) s[tid * KTOP + k] = loc[k];
    __syncthreads();
    for (int round = 0; round < KTOP; round++) {
        float bv = -3.4e38f; int bi = 0;
#pragma unroll
        for (int k = 0; k < KTOP; k++) {
            float v = s[tid * KTOP + k];
            if (v > bv) { bv = v; bi = tid * KTOP + k; }
        }
        rv[tid] = bv; ri[tid] = bi;
        __syncthreads();
        for (int st = 128; st > 0; st >>= 1) {
            if (tid < st && rv[tid + st] > rv[tid]) { rv[tid] = rv[tid + st]; ri[tid] = ri[tid + st]; }
            __syncthreads();
        }
        if (round == KTOP - 1) {
            if (tid == 0) g_kth = rv[0];
        } else {
            if (tid == 0) s[ri[0]] = -3.4e38f;   // remove ONE instance (duplicates ok)
            __syncthreads();
        }
    }
}

// ---------------- 3) adjacency structure (deterministic, no atomics) ---------
__global__ void k_rows() {
    int i = threadIdx.x;
    float kth = g_kth;
    int cnt = 0;
    const float* Ai = g_A + i * NN;
    for (int j = 0; j < NN; j++) {
        if (Ai[j] > kth && cnt < RMAX) { g_cols[i][cnt] = j; cnt++; }
    }
    g_rowCnt[i]   = cnt;
    g_rIndexOf[i] = -1;
    g_dIndexOf[i] = -1;
    __syncthreads();
    if (i == 0) {
        int nR = 0;
        for (int r = 0; r < NN; r++)
            if (g_rowCnt[r] > 0 && nR < RMAX) { g_rIndexOf[r] = nR; g_rowIds[nR] = r; nR++; }
        g_nRows = nR;
        int nD = 0;
        for (int rr = 0; rr < nR; rr++) {
            int row = g_rowIds[rr];
            for (int k = 0; k < g_rowCnt[row]; k++) {
                int j = g_cols[row][k];
                if (g_dIndexOf[j] < 0 && nD < RMAX) { g_dIndexOf[j] = nD; g_dCols[nD] = j; nD++; }
            }
        }
        g_nD = nD;
    }
}

// ---------------- 4) write adj to output ----------------
__global__ void k_adj(float* __restrict__ adj) {
    int idx = blockIdx.x * 256 + threadIdx.x;
    adj[idx] = (g_A[idx] > g_kth) ? 1.f : 0.f;
}

// ---------------- 5) w1[h] = W_h @ a1_h, w2[h] = W_h @ a2_h ----------------
__global__ void k_w12(const float* __restrict__ W, const float* __restrict__ a) {
    __shared__ float sa[2 * HF];
    int h = blockIdx.x, tid = threadIdx.x;
    if (tid < 2 * HF) sa[tid] = a[h * 2 * HF + tid];
    __syncthreads();
    const float4* Wv = (const float4*)(W + (size_t)h * FIN * HF + (size_t)tid * HF);
    float w1 = 0.f, w2 = 0.f;
#pragma unroll
    for (int c4 = 0; c4 < HF / 4; c4++) {
        float4 w = Wv[c4];
        int c = c4 * 4;
        w1 += w.x * sa[c] + w.y * sa[c + 1] + w.z * sa[c + 2] + w.w * sa[c + 3];
        w2 += w.x * sa[HF + c] + w.y * sa[HF + c + 1] + w.z * sa[HF + c + 2] + w.w * sa[HF + c + 3];
    }
    g_w1[h * FIN + tid] = w1;
    g_w2[h * FIN + tid] = w2;
}

// ---------------- 6) E2[h][j] = X[j] . w2[h]  (512x512x256 GEMM) -------------
__global__ void k_e2(const float* __restrict__ X) {
    __shared__ float sX[32][33];
    __shared__ float sW[32][33];
    int tx = threadIdx.x, ty = threadIdx.y;
    int j = blockIdx.x * 32 + tx;
    int h = blockIdx.y * 32 + ty;
    float acc = 0.f;
    for (int kk = 0; kk < FIN; kk += 32) {
        sX[ty][tx] = X[(blockIdx.x * 32 + ty) * FIN + kk + tx];
        sW[ty][tx] = g_w2[(blockIdx.y * 32 + ty) * FIN + kk + tx];
        __syncthreads();
#pragma unroll
        for (int k = 0; k < 32; k++) acc += sX[tx][k] * sW[ty][k];
        __syncthreads();
    }
    g_e2[h * NN + j] = acc;
}

// ---------------- 7) e1 for rows in R only ----------------
__global__ void k_e1R(const float* __restrict__ X) {
    __shared__ float sXi[FIN];
    int r = blockIdx.x, tid = threadIdx.x;
    int nR = g_nRows;
    int i = (r < nR) ? g_rowIds[r] : 0;
    sXi[tid]       = X[i * FIN + tid];
    sXi[tid + 128] = X[i * FIN + tid + 128];
    __syncthreads();
    if (r >= nR) return;
    int h = blockIdx.y * 128 + tid;
    const float* w1 = g_w1 + h * FIN;
    float acc = 0.f;
#pragma unroll 8
    for (int f = 0; f < FIN; f++) acc += sXi[f] * w1[f];
    g_e1R[r * NN + h] = acc;
}

// ------- 8) Wh columns: WhC[h][jd][c] = X[dCols[jd]] @ W_h  (W read once) ----
__global__ void k_whc(const float* __restrict__ X, const float* __restrict__ W) {
    __shared__ float sXd[RMAX][FIN];           // 16 KB (zero-padded beyond nD)
    __shared__ float sRed[4][RMAX][HF + 1];    // ~16.6 KB
    int h = blockIdx.x, tid = threadIdx.x;
    int nD = g_nD;
    for (int idx = tid; idx < RMAX * FIN; idx += 256) {
        int jd = idx / FIN, f = idx % FIN;
        sXd[jd][f] = (jd < nD) ? X[g_dCols[jd] * FIN + f] : 0.f;
    }
    __syncthreads();
    int c = tid & 63, fg = tid >> 6;
    float acc[RMAX];
#pragma unroll
    for (int jd = 0; jd < RMAX; jd++) acc[jd] = 0.f;
    const float* Wh = W + (size_t)h * FIN * HF;
    for (int f = fg * 64; f < fg * 64 + 64; f++) {
        float wv = Wh[f * HF + c];
#pragma unroll
        for (int jd = 0; jd < RMAX; jd++) acc[jd] += sXd[jd][f] * wv;
    }
#pragma unroll
    for (int jd = 0; jd < RMAX; jd++) sRed[fg][jd][c] = acc[jd];
    __syncthreads();
    if (fg == 0) {
#pragma unroll
        for (int jd = 0; jd < RMAX; jd++) {
            float t = sRed[0][jd][c] + sRed[1][jd][c] + sRed[2][jd][c] + sRed[3][jd][c];
            g_WhC[(h * RMAX + jd) * HF + c] = t;
        }
    }
}

// -------- 9) per-head softmax rows (full denominator) + sparse A@Wh ----------
__global__ void k_heads() {
    __shared__ float sv[NN];
    __shared__ float sred[128];
    int slot = blockIdx.y;
    if (slot >= g_nRows) return;
    int h = blockIdx.x, tid = threadIdx.x;
    int i = g_rowIds[slot];
    float e1 = g_e1R[slot * NN + h];
    const float* e2 = g_e2 + h * NN;
    float lm = -3.4e38f;
#pragma unroll
    for (int k = 0; k < 4; k++) {
        int j = tid + k * 128;
        float v = lrelu(e1 + e2[j]);
        sv[j] = v;
        lm = fmaxf(lm, v);
    }
    sred[tid] = lm; __syncthreads();
    for (int st = 64; st > 0; st >>= 1) {
        if (tid < st) sred[tid] = fmaxf(sred[tid], sred[tid + st]);
        __syncthreads();
    }
    float m = sred[0];
    __syncthreads();
    float ls = 0.f;
#pragma unroll
    for (int k = 0; k < 4; k++) ls += expf(sv[tid + k * 128] - m);
    sred[tid] = ls; __syncthreads();
    for (int st = 64; st > 0; st >>= 1) {
        if (tid < st) sred[tid] += sred[tid + st];
        __syncthreads();
    }
    float denom = sred[0];
    if (tid < HF) {
        float acc = 0.f;
        int cnt = g_rowCnt[i];
        for (int k = 0; k < cnt; k++) {
            int j  = g_cols[i][k];
            int jd = g_dIndexOf[j];
            float coef = expf(sv[j] - m) / denom;
            acc += coef * g_WhC[(h * RMAX + jd) * HF + tid];
        }
        g_midR[slot * (NN * HF) + h * HF + tid] = eluf(acc);
    }
}

// -------- 10) Wh2 = midR @ W_out (split-K partials; W_out read once) ---------
__global__ void k_wh2(const float* __restrict__ Wout) {
    __shared__ float smid[RMAX][512];   // 32 KB
    int kb = blockIdx.x, tid = threadIdx.x;
    int nR = g_nRows;
    int k0 = kb * 512;
    for (int idx = tid; idx < RMAX * 512; idx += 256) {
        int r = idx / 512, k = idx % 512;
        smid[r][k] = (r < nR) ? g_midR[r * (NN * HF) + k0 + k] : 0.f;
    }
    __syncthreads();
    int c = tid & 63, kg = tid >> 6;
    float acc[RMAX];
#pragma unroll
    for (int r = 0; r < RMAX; r++) acc[r] = 0.f;
    for (int kk = kg * 128; kk < kg * 128 + 128; kk++) {
        float wv = Wout[(size_t)(k0 + kk) * HF + c];
#pragma unroll
        for (int r = 0; r < RMAX; r++) acc[r] += smid[r][kk] * wv;
    }
    int p = kb * 4 + kg;
#pragma unroll
    for (int r = 0; r < RMAX; r++) g_part[(p * RMAX + r) * HF + c] = acc[r];
}

// -------- 11) reduce partials; e1_2 / e2_2 ----------
__global__ void k_wh2red(const float* __restrict__ aout) {
    __shared__ float sW[RMAX][HF];
    int tid = threadIdx.x;                 // 1024 = 16 * 64
    int r = tid / HF, c = tid % HF;
    float acc = 0.f;
    for (int p = 0; p < 256; p++) acc += g_part[(p * RMAX + r) * HF + c];
    sW[r][c] = acc;
    g_Wh2[r * HF + c] = acc;
    __syncthreads();
    if (tid < RMAX) {
        float e1 = 0.f, e2 = 0.f;
        for (int cc = 0; cc < HF; cc++) {
            e1 += sW[tid][cc] * aout[cc];
            e2 += sW[tid][cc] * aout[HF + cc];
        }
        g_e12[tid] = e1;
        g_e22[tid] = e2;
    }
}

// -------- 12) second-layer softmax (closed-form denominator) + final elu -----
__global__ void k_final(const float* __restrict__ V, float* __restrict__ out) {
    __shared__ float sMD[2];
    int i = blockIdx.x, c = threadIdx.x;
    int r = g_rIndexOf[i];
    float val = 0.f;
    if (r >= 0) {
        if (c == 0) {
            int nR = g_nRows;
            float e1 = g_e12[r];
            float base = lrelu(e1);             // columns j not in R have e2 = 0
            float m = base;
            for (int rr = 0; rr < nR; rr++) m = fmaxf(m, lrelu(e1 + g_e22[rr]));
            float den = (float)(NN - nR) * expf(base - m);
            for (int rr = 0; rr < nR; rr++) den += expf(lrelu(e1 + g_e22[rr]) - m);
            sMD[0] = m; sMD[1] = den;
        }
        __syncthreads();
        float m = sMD[0], den = sMD[1];
        float e1 = g_e12[r];
        float acc = 0.f;
        int cnt = g_rowCnt[i];
        for (int k = 0; k < cnt; k++) {
            int j  = g_cols[i][k];
            int rj = g_rIndexOf[j];
            if (rj >= 0) {                      // rj < 0: Wh2 row is zero
                float coef = expf(lrelu(e1 + g_e22[rj]) - m) / den;
                acc += coef * g_Wh2[rj * HF + c];
            }
        }
        val = eluf(V[i * HF + c] * eluf(acc));
    }
    out[i * HF + c] = val;
}

// ---------------- launcher ----------------
extern "C" void kernel_launch(void* const* d_in, const int* in_sizes, int n_in,
                              void* d_out, int out_size) {
    const float* X    = (const float*)d_in[0];
    const float* Wst  = (const float*)d_in[1];
    const float* ast  = (const float*)d_in[2];
    const float* Wout = (const float*)d_in[3];
    const float* aout = (const float*)d_in[4];
    const float* V    = (const float*)d_in[5];

    float* base = (float*)d_out;
    float* adjP = nullptr;
    float* finP = nullptr;
    if (out_size >= NN * NN + NN * HF)      { adjP = base; finP = base + NN * NN; }
    else if (out_size == NN * HF)           { finP = base; }
    else if (out_size == NN * NN)           { adjP = base; }
    else                                    { finP = base; }  // fallback

    k_vvt<<<NN, NN>>>(V);
    k_topk<<<1, 256>>>();
    k_rows<<<1, NN>>>();
    if (adjP) k_adj<<<NN * NN / 256, 256>>>(adjP);
    k_w12<<<NN, FIN>>>(Wst, ast);
    k_e2<<<dim3(16, 16), dim3(32, 32)>>>(X);
    k_e1R<<<dim3(RMAX, 4), 128>>>(X);
    k_whc<<<NN, 256>>>(X, Wst);
    k_heads<<<dim3(NN, RMAX), 128>>>();
    k_wh2<<<64, 256>>>(Wout);
    k_wh2red<<<1, 1024>>>(aout);
    if (finP) k_final<<<NN, HF>>>(V, finP);
}

// round 3
// speedup vs baseline: 1.8432x; 1.8432x over previous
#include <cuda_runtime.h>
#include <math.h>

#define NN   512
#define FIN  256
#define HF   64
#define KTOP 12
#define LALPHA 0.2f
#define RMAX 16     // strict > kth(12th largest) gives <= 11 adjacency entries
#define UMAX 24     // union of adjacency columns and adjacency rows: <= 22
#define NEGINF -3.4e38f

// ---------------- scratch (__device__ globals; no allocation) ----------------
__device__ float g_A[NN * NN];            // V @ V^T
__device__ float g_cand[64 * KTOP];       // per-block top-12 candidates
__device__ float g_kth;
__device__ int   g_rowCnt[NN];
__device__ int   g_cols[NN][RMAX];        // adjacency columns per row (ascending)
__device__ int   g_nRows;
__device__ int   g_rowIds[RMAX];
__device__ int   g_rIndexOf[NN];          // node -> slot in R, or -1
__device__ int   g_nD;
__device__ int   g_dIndexOf[NN];          // node -> index in U (first nD slots), or -1
__device__ int   g_nU;
__device__ int   g_uList[UMAX];           // union: distinct adj cols, then extra adj rows
__device__ int   g_uRowIdx[RMAX];         // slot -> index in U of that row
__device__ float g_w2[NN * FIN];          // W_h @ a2_h
__device__ float g_e2[NN * NN];           // e2[h][j] = X[j] . w2[h]
__device__ float g_WhC[NN * UMAX * HF];   // Wh[h][u][c] for u in U
__device__ float g_midR[RMAX * NN * HF];  // nonzero rows of mid (16 x 32768)
__device__ float g_part[256 * RMAX * HF]; // Wh2 partials (deterministic reduce)
__device__ float g_Wh2[RMAX * HF];
__device__ float g_e12[RMAX];
__device__ float g_e22[RMAX];

__device__ __forceinline__ float lrelu(float x) { return x > 0.f ? x : LALPHA * x; }
__device__ __forceinline__ float eluf(float x)  { return x > 0.f ? x : expm1f(x); }

// ---------------- 1) A = V @ V^T ----------------
__global__ void k_vvt(const float* __restrict__ V) {
    __shared__ float sVi[HF];
    int i = blockIdx.x, tid = threadIdx.x;
    if (tid < HF) sVi[tid] = V[i * HF + tid];
    __syncthreads();
    float acc = 0.f;
    const float* Vj = V + tid * HF;
#pragma unroll
    for (int k = 0; k < HF; k++) acc += sVi[k] * Vj[k];
    g_A[i * NN + tid] = acc;
}

// ---------------- 2a) per-block top-12 (64 blocks) ----------------
__global__ void k_topkA() {
    __shared__ float s[256 * KTOP];
    __shared__ float rv[256];
    __shared__ int   ri[256];
    int tid = threadIdx.x;
    int base = blockIdx.x * (NN * NN / 64);       // 4096 per block
    float loc[KTOP];
#pragma unroll
    for (int k = 0; k < KTOP; k++) loc[k] = NEGINF;   // ascending, loc[0] = min
    for (int idx = tid; idx < NN * NN / 64; idx += 256) {
        float v = g_A[base + idx];
        if (v > loc[0]) {
            loc[0] = v;
#pragma unroll
            for (int k = 0; k < KTOP - 1; k++)
                if (loc[k] > loc[k + 1]) { float t = loc[k]; loc[k] = loc[k + 1]; loc[k + 1] = t; }
        }
    }
#pragma unroll
    for (int k = 0; k < KTOP; k++) s[tid * KTOP + k] = loc[k];
    __syncthreads();
    for (int round = 0; round < KTOP; round++) {
        float bv = NEGINF; int bi = 0;
#pragma unroll
        for (int k = 0; k < KTOP; k++) {
            float v = s[tid * KTOP + k];
            if (v > bv) { bv = v; bi = tid * KTOP + k; }
        }
        rv[tid] = bv; ri[tid] = bi;
        __syncthreads();
        for (int st = 128; st > 0; st >>= 1) {
            if (tid < st && rv[tid + st] > rv[tid]) { rv[tid] = rv[tid + st]; ri[tid] = ri[tid + st]; }
            __syncthreads();
        }
        if (tid == 0) {
            g_cand[blockIdx.x * KTOP + round] = rv[0];
            s[ri[0]] = NEGINF;
        }
        __syncthreads();
    }
}

// ---------------- 2b) merge 64*12 candidates -> 12th largest ----------------
__global__ void k_topkB() {
    __shared__ float s[256 * KTOP];
    __shared__ float rv[256];
    __shared__ int   ri[256];
    int tid = threadIdx.x;
    float loc[KTOP];
#pragma unroll
    for (int k = 0; k < KTOP; k++) loc[k] = NEGINF;
    for (int idx = tid; idx < 64 * KTOP; idx += 256) {
        float v = g_cand[idx];
        if (v > loc[0]) {
            loc[0] = v;
#pragma unroll
            for (int k = 0; k < KTOP - 1; k++)
                if (loc[k] > loc[k + 1]) { float t = loc[k]; loc[k] = loc[k + 1]; loc[k + 1] = t; }
        }
    }
#pragma unroll
    for (int k = 0; k < KTOP; k++) s[tid * KTOP + k] = loc[k];
    __syncthreads();
    for (int round = 0; round < KTOP; round++) {
        float bv = NEGINF; int bi = 0;
#pragma unroll
        for (int k = 0; k < KTOP; k++) {
            float v = s[tid * KTOP + k];
            if (v > bv) { bv = v; bi = tid * KTOP + k; }
        }
        rv[tid] = bv; ri[tid] = bi;
        __syncthreads();
        for (int st = 128; st > 0; st >>= 1) {
            if (tid < st && rv[tid + st] > rv[tid]) { rv[tid] = rv[tid + st]; ri[tid] = ri[tid + st]; }
            __syncthreads();
        }
        if (round == KTOP - 1) {
            if (tid == 0) g_kth = rv[0];
        } else {
            if (tid == 0) s[ri[0]] = NEGINF;
            __syncthreads();
        }
    }
}

// ------- 3) warp-per-row adjacency scan (coalesced) + adj output write -------
__global__ void k_rowscan(float* __restrict__ adj, int hasAdj) {
    int warp = threadIdx.x >> 5, lane = threadIdx.x & 31;
    int i = blockIdx.x * 8 + warp;
    float kth = g_kth;
    int cnt = 0;
#pragma unroll
    for (int t = 0; t < 16; t++) {
        int j = t * 32 + lane;
        float v = g_A[i * NN + j];
        bool p = v > kth;
        if (hasAdj) adj[i * NN + j] = p ? 1.f : 0.f;
        unsigned mask = __ballot_sync(0xffffffffu, p);
        if (p) {
            int pos = cnt + __popc(mask & ((1u << lane) - 1u));
            if (pos < RMAX) g_cols[i][pos] = j;
        }
        cnt += __popc(mask);
    }
    if (lane == 0) g_rowCnt[i] = cnt < RMAX ? cnt : RMAX;
    int gt = blockIdx.x * 256 + threadIdx.x;
    if (gt < NN) { g_rIndexOf[gt] = -1; g_dIndexOf[gt] = -1; }
}

// -------- 4) build row/col index structures (shared-memory serial) -----------
__global__ void k_rows2() {
    __shared__ int sCnt[NN];
    __shared__ int sCols[NN][RMAX];
    __shared__ int sD[NN];
    int tid = threadIdx.x;                          // 512 threads
    sCnt[tid] = g_rowCnt[tid];
    sD[tid] = -1;
#pragma unroll
    for (int k = 0; k < RMAX; k++) sCols[tid][k] = g_cols[tid][k];
    __syncthreads();
    if (tid == 0) {
        int rowIds[RMAX];
        int nR = 0;
        for (int r = 0; r < NN; r++)
            if (sCnt[r] > 0 && nR < RMAX) {
                g_rIndexOf[r] = nR; g_rowIds[nR] = r; rowIds[nR] = r; nR++;
            }
        g_nRows = nR;
        int nD = 0;
        for (int rr = 0; rr < nR; rr++) {
            int row = rowIds[rr];
            int c = sCnt[row];
            for (int k = 0; k < c; k++) {
                int j = sCols[row][k];
                if (sD[j] < 0 && nD < UMAX) {
                    sD[j] = nD; g_dIndexOf[j] = nD; g_uList[nD] = j; nD++;
                }
            }
        }
        g_nD = nD;
        int nU = nD;
        for (int rr = 0; rr < nR; rr++) {
            int i = rowIds[rr];
            if (sD[i] >= 0) g_uRowIdx[rr] = sD[i];
            else if (nU < UMAX) { g_uRowIdx[rr] = nU; g_uList[nU] = i; sD[i] = nU; nU++; }
        }
        g_nU = nU;
        for (int u = nU; u < UMAX; u++) g_uList[u] = 0;
    }
}

// ---- 5) single pass over W_stack: WhC[h][u][:] for u in U, and w2[h][:] -----
__global__ void k_wstack(const float* __restrict__ X, const float* __restrict__ W,
                         const float* __restrict__ a) {
    __shared__ float sXd[UMAX][FIN];     // 24 KB, zero-padded beyond nU
    __shared__ float sa2[HF];
    __shared__ float sw2p[FIN][2];
    int h = blockIdx.x, tid = threadIdx.x;   // 64 threads
    int nU = g_nU;
    for (int idx = tid; idx < UMAX * FIN; idx += 64) {
        int u = idx / FIN, f = idx % FIN;
        sXd[u][f] = (u < nU) ? X[g_uList[u] * FIN + f] : 0.f;
    }
    sa2[tid] = a[h * 2 * HF + HF + tid];
    __syncthreads();
    int c = tid, warp = tid >> 5, lane = tid & 31;
    float acc[UMAX];
#pragma unroll
    for (int u = 0; u < UMAX; u++) acc[u] = 0.f;
    const float* Wh = W + (size_t)h * FIN * HF;
#pragma unroll 4
    for (int f = 0; f < FIN; f++) {
        float wv = Wh[f * HF + c];
#pragma unroll
        for (int u = 0; u < UMAX; u++) acc[u] += sXd[u][f] * wv;
        float pv = wv * sa2[c];
#pragma unroll
        for (int o = 16; o > 0; o >>= 1) pv += __shfl_down_sync(0xffffffffu, pv, o);
        if (lane == 0) sw2p[f][warp] = pv;
    }
    __syncthreads();
    for (int f = tid; f < FIN; f += 64) g_w2[h * FIN + f] = sw2p[f][0] + sw2p[f][1];
#pragma unroll
    for (int u = 0; u < UMAX; u++) g_WhC[(h * UMAX + u) * HF + c] = acc[u];
}

// ---------------- 6) E2[h][j] = X[j] . w2[h]  (512x512x256 GEMM) -------------
__global__ void k_e2(const float* __restrict__ X) {
    __shared__ float sX[32][33];
    __shared__ float sW[32][33];
    int tx = threadIdx.x, ty = threadIdx.y;
    int j = blockIdx.x * 32 + tx;
    int h = blockIdx.y * 32 + ty;
    float acc = 0.f;
    for (int kk = 0; kk < FIN; kk += 32) {
        sX[ty][tx] = X[(blockIdx.x * 32 + ty) * FIN + kk + tx];
        sW[ty][tx] = g_w2[(blockIdx.y * 32 + ty) * FIN + kk + tx];
        __syncthreads();
#pragma unroll
        for (int k = 0; k < 32; k++) acc += sX[tx][k] * sW[ty][k];
        __syncthreads();
    }
    g_e2[h * NN + j] = acc;
}

// --- 7) warp-per-(slot,head): e1 inline, online softmax, sparse A@Wh, elu ----
__global__ void k_heads(const float* __restrict__ a_stack) {
    __shared__ float scoef[8][RMAX];
    __shared__ int   sjd[8][RMAX];
    int slot = blockIdx.y;
    if (slot >= g_nRows) return;
    int warp = threadIdx.x >> 5, lane = threadIdx.x & 31;
    int h = blockIdx.x * 8 + warp;
    int i = g_rowIds[slot];
    int ui = g_uRowIdx[slot];
    // e1 = WhC[h][ui][:] . a1_h
    const float* whU = g_WhC + (h * UMAX + ui) * HF;
    const float* a1  = a_stack + (size_t)h * 2 * HF;
    float p = whU[lane] * a1[lane] + whU[lane + 32] * a1[lane + 32];
#pragma unroll
    for (int o = 16; o > 0; o >>= 1) p += __shfl_xor_sync(0xffffffffu, p, o);
    float e1 = p;
    // online softmax over the full row (denominator BEFORE masking)
    const float* e2 = g_e2 + h * NN;
    float m = NEGINF, s = 0.f;
#pragma unroll
    for (int t = 0; t < 16; t++) {
        float v = lrelu(e1 + e2[t * 32 + lane]);
        if (v > m) { s = s * expf(m - v) + 1.f; m = v; }
        else       { s += expf(v - m); }
    }
#pragma unroll
    for (int o = 16; o > 0; o >>= 1) {
        float m2 = __shfl_xor_sync(0xffffffffu, m, o);
        float s2 = __shfl_xor_sync(0xffffffffu, s, o);
        float M = fmaxf(m, m2);
        s = s * expf(m - M) + s2 * expf(m2 - M);
        m = M;
    }
    int cnt = g_rowCnt[i];
    if (lane < cnt) {
        int j = g_cols[i][lane];
        sjd[warp][lane]   = g_dIndexOf[j];
        scoef[warp][lane] = expf(lrelu(e1 + e2[j]) - m) / s;
    }
    __syncwarp();
    float acc0 = 0.f, acc1 = 0.f;
    for (int k = 0; k < cnt; k++) {
        float cf = scoef[warp][k];
        const float* whc = g_WhC + (h * UMAX + sjd[warp][k]) * HF;
        acc0 += cf * whc[lane];
        acc1 += cf * whc[lane + 32];
    }
    float* dst = g_midR + (size_t)slot * (NN * HF) + h * HF;
    dst[lane]      = eluf(acc0);
    dst[lane + 32] = eluf(acc1);
}

// -------- 8) Wh2 = midR @ W_out (split-K partials; W_out read once) ----------
__global__ void k_wh2(const float* __restrict__ Wout) {
    __shared__ float smid[RMAX][512];   // 32 KB
    int kb = blockIdx.x, tid = threadIdx.x;
    int nR = g_nRows;
    int k0 = kb * 512;
    for (int idx = tid; idx < RMAX * 512; idx += 256) {
        int r = idx / 512, k = idx % 512;
        smid[r][k] = (r < nR) ? g_midR[(size_t)r * (NN * HF) + k0 + k] : 0.f;
    }
    __syncthreads();
    int c = tid & 63, kg = tid >> 6;
    float acc[RMAX];
#pragma unroll
    for (int r = 0; r < RMAX; r++) acc[r] = 0.f;
    for (int kk = kg * 128; kk < kg * 128 + 128; kk++) {
        float wv = Wout[(size_t)(k0 + kk) * HF + c];
#pragma unroll
        for (int r = 0; r < RMAX; r++) acc[r] += smid[r][kk] * wv;
    }
    int pp = kb * 4 + kg;
#pragma unroll
    for (int r = 0; r < RMAX; r++) g_part[(pp * RMAX + r) * HF + c] = acc[r];
}

// -------- 9) reduce partials (16 blocks); e1_2 / e2_2 ----------
__global__ void k_wh2red(const float* __restrict__ aout) {
    __shared__ float sW[HF];
    int r = blockIdx.x, c = threadIdx.x;     // 16 blocks x 64 threads
    float acc = 0.f;
#pragma unroll 8
    for (int pp = 0; pp < 256; pp++) acc += g_part[(pp * RMAX + r) * HF + c];
    g_Wh2[r * HF + c] = acc;
    sW[c] = acc;
    __syncthreads();
    if (c < 2) {
        const float* av = aout + c * HF;
        float e = 0.f;
        for (int cc = 0; cc < HF; cc++) e += sW[cc] * av[cc];
        if (c == 0) g_e12[r] = e; else g_e22[r] = e;
    }
}

// -------- 10) second-layer softmax (closed-form denominator) + final elu -----
__global__ void k_final(const float* __restrict__ V, float* __restrict__ out) {
    __shared__ float sMD[2];
    int i = blockIdx.x, c = threadIdx.x;
    int r = g_rIndexOf[i];
    float val = 0.f;
    if (r >= 0) {
        if (c == 0) {
            int nR = g_nRows;
            float e1 = g_e12[r];
            float base = lrelu(e1);             // columns j not in R have e2 = 0
            float m = base;
            for (int rr = 0; rr < nR; rr++) m = fmaxf(m, lrelu(e1 + g_e22[rr]));
            float den = (float)(NN - nR) * expf(base - m);
            for (int rr = 0; rr < nR; rr++) den += expf(lrelu(e1 + g_e22[rr]) - m);
            sMD[0] = m; sMD[1] = den;
        }
        __syncthreads();
        float m = sMD[0], den = sMD[1];
        float e1 = g_e12[r];
        float acc = 0.f;
        int cnt = g_rowCnt[i];
        for (int k = 0; k < cnt; k++) {
            int j  = g_cols[i][k];
            int rj = g_rIndexOf[j];
            if (rj >= 0) {                      // rj < 0: Wh2 row is zero
                float coef = expf(lrelu(e1 + g_e22[rj]) - m) / den;
                acc += coef * g_Wh2[rj * HF + c];
            }
        }
        val = eluf(V[i * HF + c] * eluf(acc));
    }
    out[i * HF + c] = val;
}

// ---------------- launcher ----------------
extern "C" void kernel_launch(void* const* d_in, const int* in_sizes, int n_in,
                              void* d_out, int out_size) {
    const float* X    = (const float*)d_in[0];
    const float* Wst  = (const float*)d_in[1];
    const float* ast  = (const float*)d_in[2];
    const float* Wout = (const float*)d_in[3];
    const float* aout = (const float*)d_in[4];
    const float* V    = (const float*)d_in[5];

    float* base = (float*)d_out;
    float* adjP = nullptr;
    float* finP = nullptr;
    if (out_size >= NN * NN + NN * HF)      { adjP = base; finP = base + NN * NN; }
    else if (out_size == NN * HF)           { finP = base; }
    else if (out_size == NN * NN)           { adjP = base; }
    else                                    { finP = base; }

    k_vvt<<<NN, NN>>>(V);
    k_topkA<<<64, 256>>>();
    k_topkB<<<1, 256>>>();
    k_rowscan<<<64, 256>>>(adjP, adjP != nullptr);
    k_rows2<<<1, NN>>>();
    k_wstack<<<NN, 64>>>(X, Wst, ast);
    k_e2<<<dim3(16, 16), dim3(32, 32)>>>(X);
    k_heads<<<dim3(64, RMAX), 256>>>(ast);
    k_wh2<<<64, 256>>>(Wout);
    k_wh2red<<<RMAX, HF>>>(aout);
    if (finP) k_final<<<NN, HF>>>(V, finP);
}

// round 4
// speedup vs baseline: 2.5268x; 1.3709x over previous
#include <cuda_runtime.h>
#include <math.h>

#define NN   512
#define FIN  256
#define HF   64
#define KTOP 12
#define LALPHA 0.2f
#define RMAX 16     // strict > kth(12th largest) gives <= 11 adjacency entries
#define UMAX 24     // union of adjacency columns and adjacency rows: <= 22
#define NEGINF -3.4e38f

// ---------------- scratch (__device__ globals; no allocation) ----------------
__device__ __align__(16) float g_A[NN * NN];            // V @ V^T
__device__ float g_cand[64 * KTOP];
__device__ float g_kth;
__device__ int   g_rowCnt[NN];
__device__ int   g_cols[NN][RMAX];
__device__ int   g_nRows;
__device__ int   g_rowIds[RMAX];
__device__ int   g_rIndexOf[NN];
__device__ int   g_nD;
__device__ int   g_dIndexOf[NN];
__device__ int   g_nU;
__device__ int   g_uList[UMAX];
__device__ int   g_uRowIdx[RMAX];
__device__ __align__(16) float g_w2[NN * FIN];
__device__ __align__(16) float g_e2[NN * NN];
__device__ __align__(16) float g_WhC[NN * UMAX * HF];
__device__ __align__(16) float g_midR[RMAX * NN * HF];
__device__ __align__(16) float g_part[256 * RMAX * HF];
__device__ float g_Wh2[RMAX * HF];
__device__ float g_e12[RMAX];
__device__ float g_e22[RMAX];

__device__ __forceinline__ float lrelu(float x) { return x > 0.f ? x : LALPHA * x; }
__device__ __forceinline__ float eluf(float x)  { return x > 0.f ? x : expm1f(x); }

// ---------------- 1) A = V @ V^T ----------------
__global__ void k_vvt(const float* __restrict__ V) {
    __shared__ float sVi[HF];
    int i = blockIdx.x, tid = threadIdx.x;
    if (tid < HF) sVi[tid] = V[i * HF + tid];
    __syncthreads();
    float acc = 0.f;
    const float* Vj = V + tid * HF;
#pragma unroll
    for (int k = 0; k < HF; k++) acc += sVi[k] * Vj[k];
    g_A[i * NN + tid] = acc;
}

// ---------------- 2a) per-block top-12 (64 blocks) ----------------
__global__ void k_topkA() {
    __shared__ float s[256 * KTOP];
    __shared__ float rv[256];
    __shared__ int   ri[256];
    int tid = threadIdx.x;
    int base = blockIdx.x * (NN * NN / 64);
    float loc[KTOP];
#pragma unroll
    for (int k = 0; k < KTOP; k++) loc[k] = NEGINF;
    for (int idx = tid; idx < NN * NN / 64; idx += 256) {
        float v = g_A[base + idx];
        if (v > loc[0]) {
            loc[0] = v;
#pragma unroll
            for (int k = 0; k < KTOP - 1; k++)
                if (loc[k] > loc[k + 1]) { float t = loc[k]; loc[k] = loc[k + 1]; loc[k + 1] = t; }
        }
    }
#pragma unroll
    for (int k = 0; k < KTOP; k++) s[tid * KTOP + k] = loc[k];
    __syncthreads();
    for (int round = 0; round < KTOP; round++) {
        float bv = NEGINF; int bi = 0;
#pragma unroll
        for (int k = 0; k < KTOP; k++) {
            float v = s[tid * KTOP + k];
            if (v > bv) { bv = v; bi = tid * KTOP + k; }
        }
        rv[tid] = bv; ri[tid] = bi;
        __syncthreads();
        for (int st = 128; st > 0; st >>= 1) {
            if (tid < st && rv[tid + st] > rv[tid]) { rv[tid] = rv[tid + st]; ri[tid] = ri[tid + st]; }
            __syncthreads();
        }
        if (tid == 0) {
            g_cand[blockIdx.x * KTOP + round] = rv[0];
            s[ri[0]] = NEGINF;
        }
        __syncthreads();
    }
}

// ---------------- 2b) merge candidates -> 12th largest ----------------
__global__ void k_topkB() {
    __shared__ float s[256 * KTOP];
    __shared__ float rv[256];
    __shared__ int   ri[256];
    int tid = threadIdx.x;
    float loc[KTOP];
#pragma unroll
    for (int k = 0; k < KTOP; k++) loc[k] = NEGINF;
    for (int idx = tid; idx < 64 * KTOP; idx += 256) {
        float v = g_cand[idx];
        if (v > loc[0]) {
            loc[0] = v;
#pragma unroll
            for (int k = 0; k < KTOP - 1; k++)
                if (loc[k] > loc[k + 1]) { float t = loc[k]; loc[k] = loc[k + 1]; loc[k + 1] = t; }
        }
    }
#pragma unroll
    for (int k = 0; k < KTOP; k++) s[tid * KTOP + k] = loc[k];
    __syncthreads();
    for (int round = 0; round < KTOP; round++) {
        float bv = NEGINF; int bi = 0;
#pragma unroll
        for (int k = 0; k < KTOP; k++) {
            float v = s[tid * KTOP + k];
            if (v > bv) { bv = v; bi = tid * KTOP + k; }
        }
        rv[tid] = bv; ri[tid] = bi;
        __syncthreads();
        for (int st = 128; st > 0; st >>= 1) {
            if (tid < st && rv[tid + st] > rv[tid]) { rv[tid] = rv[tid + st]; ri[tid] = ri[tid + st]; }
            __syncthreads();
        }
        if (round == KTOP - 1) {
            if (tid == 0) g_kth = rv[0];
        } else {
            if (tid == 0) s[ri[0]] = NEGINF;
            __syncthreads();
        }
    }
}

// ------- 3) warp-per-row adjacency scan: prefetch 16 (MLP=16) then ballot ----
__global__ void k_rowscan(float* __restrict__ adj, int hasAdj) {
    int warp = threadIdx.x >> 5, lane = threadIdx.x & 31;
    int i = blockIdx.x * 8 + warp;
    float kth = g_kth;
    float v[16];
#pragma unroll
    for (int t = 0; t < 16; t++) v[t] = g_A[i * NN + t * 32 + lane];
    int cnt = 0;
#pragma unroll
    for (int t = 0; t < 16; t++) {
        bool p = v[t] > kth;
        if (hasAdj) adj[i * NN + t * 32 + lane] = p ? 1.f : 0.f;
        unsigned mask = __ballot_sync(0xffffffffu, p);
        if (p) {
            int pos = cnt + __popc(mask & ((1u << lane) - 1u));
            if (pos < RMAX) g_cols[i][pos] = t * 32 + lane;
        }
        cnt += __popc(mask);
    }
    if (lane == 0) g_rowCnt[i] = cnt < RMAX ? cnt : RMAX;
    int gt = blockIdx.x * 256 + threadIdx.x;
    if (gt < NN) { g_rIndexOf[gt] = -1; g_dIndexOf[gt] = -1; }
}

// -------- 4) build index structures (ballot-assisted serial tail) ------------
__global__ void k_rows2() {
    __shared__ int sCnt[NN];
    __shared__ int sCols[NN][RMAX];
    __shared__ int sD[NN];
    __shared__ unsigned sMask[16];
    int tid = threadIdx.x;                          // 512 threads
    int cnt = g_rowCnt[tid];
    sCnt[tid] = cnt;
    sD[tid] = -1;
#pragma unroll
    for (int k = 0; k < RMAX; k++) sCols[tid][k] = g_cols[tid][k];
    unsigned wm = __ballot_sync(0xffffffffu, cnt > 0);
    if ((tid & 31) == 0) sMask[tid >> 5] = wm;
    __syncthreads();
    if (tid == 0) {
        int rowIds[RMAX];
        int nR = 0;
        for (int w = 0; w < 16; w++) {
            unsigned m = sMask[w];
            while (m && nR < RMAX) {
                int b = __ffs(m) - 1; m &= m - 1;
                int r = w * 32 + b;
                g_rIndexOf[r] = nR; g_rowIds[nR] = r; rowIds[nR] = r; nR++;
            }
        }
        g_nRows = nR;
        int nD = 0;
        for (int rr = 0; rr < nR; rr++) {
            int row = rowIds[rr];
            int c = sCnt[row];
            for (int k = 0; k < c; k++) {
                int j = sCols[row][k];
                if (sD[j] < 0 && nD < UMAX) {
                    sD[j] = nD; g_dIndexOf[j] = nD; g_uList[nD] = j; nD++;
                }
            }
        }
        g_nD = nD;
        int nU = nD;
        for (int rr = 0; rr < nR; rr++) {
            int i = rowIds[rr];
            if (sD[i] >= 0) g_uRowIdx[rr] = sD[i];
            else if (nU < UMAX) { g_uRowIdx[rr] = nU; g_uList[nU] = i; sD[i] = nU; nU++; }
        }
        g_nU = nU;
        for (int u = nU; u < UMAX; u++) g_uList[u] = 0;
    }
}

// ---- 5) single pass over W_stack: WhC + w2 (256 threads, templated U) -------
template<int U>
__device__ __forceinline__ void wstack_body(float* sbuf, const float* sa2,
        float (*sw2p)[2], const float* __restrict__ X,
        const float* __restrict__ W, int h, int tid, int nU) {
    float (*sXd)[FIN] = (float(*)[FIN])sbuf;
    for (int idx = tid; idx < U * FIN; idx += 256) {
        int u = idx / FIN, f = idx % FIN;
        sXd[u][f] = (u < nU) ? X[g_uList[u] * FIN + f] : 0.f;
    }
    __syncthreads();
    int fg = tid >> 6, c = tid & 63, lane = tid & 31, half = (c >> 5) & 1;
    float acc[U];
#pragma unroll
    for (int u = 0; u < U; u++) acc[u] = 0.f;
    const float* Wh = W + (size_t)h * FIN * HF;
    float a2c = sa2[c];
    for (int f = fg * 64; f < fg * 64 + 64; f++) {
        float wv = Wh[f * HF + c];
#pragma unroll
        for (int u = 0; u < U; u++) acc[u] += sXd[u][f] * wv;
        float pv = wv * a2c;
#pragma unroll
        for (int o = 16; o > 0; o >>= 1) pv += __shfl_down_sync(0xffffffffu, pv, o);
        if (lane == 0) sw2p[f][half] = pv;
    }
    __syncthreads();                                    // sXd reads done
    g_w2[h * FIN + tid] = sw2p[tid][0] + sw2p[tid][1];  // tid covers f=0..255
    float (*sRed)[UMAX][HF + 1] = (float(*)[UMAX][HF + 1])sbuf;  // overlays sXd
#pragma unroll
    for (int u = 0; u < U; u++) sRed[fg][u][c] = acc[u];
    __syncthreads();
    if (fg == 0) {
#pragma unroll
        for (int u = 0; u < U; u++)
            g_WhC[(h * UMAX + u) * HF + c] =
                sRed[0][u][c] + sRed[1][u][c] + sRed[2][u][c] + sRed[3][u][c];
    }
}

__global__ void k_wstack(const float* __restrict__ X, const float* __restrict__ W,
                         const float* __restrict__ a) {
    __shared__ __align__(16) float sbuf[4 * UMAX * (HF + 1)];   // 6240 floats
    __shared__ float sa2[HF];
    __shared__ float sw2p[FIN][2];
    int h = blockIdx.x, tid = threadIdx.x;   // 256 threads
    if (tid < HF) sa2[tid] = a[h * 2 * HF + HF + tid];
    int nU = g_nU;
    if (nU <= 12)      wstack_body<12>(sbuf, sa2, sw2p, X, W, h, tid, nU);
    else if (nU <= 16) wstack_body<16>(sbuf, sa2, sw2p, X, W, h, tid, nU);
    else               wstack_body<UMAX>(sbuf, sa2, sw2p, X, W, h, tid, nU);
}

// ------- 6) E2 = w2 @ X^T  (register-tiled 64x32, 4x2 per thread) ------------
__global__ void k_e2(const float* __restrict__ X) {
    __shared__ __align__(16) float sA[32][68];   // X:   [k][j]  (64 j)
    __shared__ __align__(16) float sB[32][34];   // w2:  [k][h]  (32 h)
    int tid = threadIdx.x;                       // 256
    int j0 = blockIdx.x * 64, h0 = blockIdx.y * 32;
    int tx = tid & 15, ty = tid >> 4;
    float acc[4][2];
#pragma unroll
    for (int i = 0; i < 4; i++) { acc[i][0] = 0.f; acc[i][1] = 0.f; }
    for (int kt = 0; kt < FIN / 32; kt++) {
        int k0 = kt * 32;
#pragma unroll
        for (int l = 0; l < 2; l++) {
            int idx = tid + l * 256;
            int row = idx >> 3, q = idx & 7;
            float4 v = *(const float4*)(X + (size_t)(j0 + row) * FIN + k0 + q * 4);
            sA[q * 4 + 0][row] = v.x; sA[q * 4 + 1][row] = v.y;
            sA[q * 4 + 2][row] = v.z; sA[q * 4 + 3][row] = v.w;
        }
        {
            int row = tid >> 3, q = tid & 7;
            float4 v = *(const float4*)(g_w2 + (size_t)(h0 + row) * FIN + k0 + q * 4);
            sB[q * 4 + 0][row] = v.x; sB[q * 4 + 1][row] = v.y;
            sB[q * 4 + 2][row] = v.z; sB[q * 4 + 3][row] = v.w;
        }
        __syncthreads();
#pragma unroll
        for (int k = 0; k < 32; k++) {
            float4 av = *(const float4*)&sA[k][tx * 4];
            float b0 = sB[k][ty * 2], b1 = sB[k][ty * 2 + 1];
            acc[0][0] += av.x * b0; acc[1][0] += av.y * b0;
            acc[2][0] += av.z * b0; acc[3][0] += av.w * b0;
            acc[0][1] += av.x * b1; acc[1][1] += av.y * b1;
            acc[2][1] += av.z * b1; acc[3][1] += av.w * b1;
        }
        __syncthreads();
    }
#pragma unroll
    for (int b = 0; b < 2; b++)
#pragma unroll
        for (int i = 0; i < 4; i++)
            g_e2[(size_t)(h0 + ty * 2 + b) * NN + j0 + tx * 4 + i] = acc[i][b];
}

// --- 7) block-per-head: e2 row staged once; warp-per-slot online softmax -----
__global__ void k_heads(const float* __restrict__ a_stack) {
    __shared__ float se2[NN];
    int h = blockIdx.x, tid = threadIdx.x;       // 512 threads
    se2[tid] = g_e2[(size_t)h * NN + tid];
    __syncthreads();
    int warp = tid >> 5, lane = tid & 31;
    int nR = g_nRows;
    if (warp >= nR) return;
    int slot = warp;
    int i = g_rowIds[slot];
    int ui = g_uRowIdx[slot];
    const float* whU = g_WhC + (h * UMAX + ui) * HF;
    const float* a1  = a_stack + (size_t)h * 2 * HF;
    float p = whU[lane] * a1[lane] + whU[lane + 32] * a1[lane + 32];
#pragma unroll
    for (int o = 16; o > 0; o >>= 1) p += __shfl_xor_sync(0xffffffffu, p, o);
    float e1 = p;
    float m = NEGINF, s = 0.f;
#pragma unroll
    for (int t = 0; t < 16; t++) {
        float v = lrelu(e1 + se2[t * 32 + lane]);
        float nm = fmaxf(m, v);
        s = s * __expf(m - nm) + __expf(v - nm);
        m = nm;
    }
#pragma unroll
    for (int o = 16; o > 0; o >>= 1) {
        float m2 = __shfl_xor_sync(0xffffffffu, m, o);
        float s2 = __shfl_xor_sync(0xffffffffu, s, o);
        float M = fmaxf(m, m2);
        s = s * __expf(m - M) + s2 * __expf(m2 - M);
        m = M;
    }
    int cnt = g_rowCnt[i];
    float coef = 0.f; int jd = 0;
    if (lane < cnt) {
        int j = g_cols[i][lane];
        jd = g_dIndexOf[j];
        coef = __expf(lrelu(e1 + se2[j]) - m) / s;
    }
    float acc0 = 0.f, acc1 = 0.f;
    for (int k = 0; k < cnt; k++) {
        float cf  = __shfl_sync(0xffffffffu, coef, k);
        int   jdk = __shfl_sync(0xffffffffu, jd, k);
        const float* whc = g_WhC + (h * UMAX + jdk) * HF;
        acc0 += cf * whc[lane];
        acc1 += cf * whc[lane + 32];
    }
    float* dst = g_midR + (size_t)slot * (NN * HF) + h * HF;
    dst[lane]      = eluf(acc0);
    dst[lane + 32] = eluf(acc1);
}

// -------- 8) Wh2 = midR @ W_out (split-K partials; W_out read once) ----------
__global__ void k_wh2(const float* __restrict__ Wout) {
    __shared__ float smid[RMAX][512];   // 32 KB
    int kb = blockIdx.x, tid = threadIdx.x;
    int nR = g_nRows;
    int k0 = kb * 512;
    for (int idx = tid; idx < RMAX * 512; idx += 256) {
        int r = idx / 512, k = idx % 512;
        smid[r][k] = (r < nR) ? g_midR[(size_t)r * (NN * HF) + k0 + k] : 0.f;
    }
    __syncthreads();
    int c = tid & 63, kg = tid >> 6;
    float acc[RMAX];
#pragma unroll
    for (int r = 0; r < RMAX; r++) acc[r] = 0.f;
    for (int kk = kg * 128; kk < kg * 128 + 128; kk++) {
        float wv = Wout[(size_t)(k0 + kk) * HF + c];
#pragma unroll
        for (int r = 0; r < RMAX; r++) acc[r] += smid[r][kk] * wv;
    }
    int pp = kb * 4 + kg;
#pragma unroll
    for (int r = 0; r < RMAX; r++) g_part[(pp * RMAX + r) * HF + c] = acc[r];
}

// -------- 9) reduce partials (16 blocks); e1_2 / e2_2 ----------
__global__ void k_wh2red(const float* __restrict__ aout) {
    __shared__ float sW[HF];
    int r = blockIdx.x, c = threadIdx.x;
    float acc = 0.f;
#pragma unroll 8
    for (int pp = 0; pp < 256; pp++) acc += g_part[(pp * RMAX + r) * HF + c];
    g_Wh2[r * HF + c] = acc;
    sW[c] = acc;
    __syncthreads();
    if (c < 2) {
        const float* av = aout + c * HF;
        float e = 0.f;
        for (int cc = 0; cc < HF; cc++) e += sW[cc] * av[cc];
        if (c == 0) g_e12[r] = e; else g_e22[r] = e;
    }
}

// -------- 10) second-layer softmax (closed-form denominator) + final elu -----
__global__ void k_final(const float* __restrict__ V, float* __restrict__ out) {
    __shared__ float sMD[2];
    int i = blockIdx.x, c = threadIdx.x;
    int r = g_rIndexOf[i];
    float val = 0.f;
    if (r >= 0) {
        if (c == 0) {
            int nR = g_nRows;
            float e1 = g_e12[r];
            float base = lrelu(e1);
            float m = base;
            for (int rr = 0; rr < nR; rr++) m = fmaxf(m, lrelu(e1 + g_e22[rr]));
            float den = (float)(NN - nR) * __expf(base - m);
            for (int rr = 0; rr < nR; rr++) den += __expf(lrelu(e1 + g_e22[rr]) - m);
            sMD[0] = m; sMD[1] = den;
        }
        __syncthreads();
        float m = sMD[0], den = sMD[1];
        float e1 = g_e12[r];
        float acc = 0.f;
        int cnt = g_rowCnt[i];
        for (int k = 0; k < cnt; k++) {
            int j  = g_cols[i][k];
            int rj = g_rIndexOf[j];
            if (rj >= 0) {
                float coef = __expf(lrelu(e1 + g_e22[rj]) - m) / den;
                acc += coef * g_Wh2[rj * HF + c];
            }
        }
        val = eluf(V[i * HF + c] * eluf(acc));
    }
    out[i * HF + c] = val;
}

// ---------------- launcher ----------------
extern "C" void kernel_launch(void* const* d_in, const int* in_sizes, int n_in,
                              void* d_out, int out_size) {
    const float* X    = (const float*)d_in[0];
    const float* Wst  = (const float*)d_in[1];
    const float* ast  = (const float*)d_in[2];
    const float* Wout = (const float*)d_in[3];
    const float* aout = (const float*)d_in[4];
    const float* V    = (const float*)d_in[5];

    float* base = (float*)d_out;
    float* adjP = nullptr;
    float* finP = nullptr;
    if (out_size >= NN * NN + NN * HF)      { adjP = base; finP = base + NN * NN; }
    else if (out_size == NN * HF)           { finP = base; }
    else if (out_size == NN * NN)           { adjP = base; }
    else                                    { finP = base; }

    k_vvt<<<NN, NN>>>(V);
    k_topkA<<<64, 256>>>();
    k_topkB<<<1, 256>>>();
    k_rowscan<<<64, 256>>>(adjP, adjP != nullptr);
    k_rows2<<<1, NN>>>();
    k_wstack<<<NN, 256>>>(X, Wst, ast);
    k_e2<<<dim3(8, 16), 256>>>(X);
    k_heads<<<NN, NN>>>(ast);
    k_wh2<<<64, 256>>>(Wout);
    k_wh2red<<<RMAX, HF>>>(aout);
    if (finP) k_final<<<NN, HF>>>(V, finP);
}

// round 5
// speedup vs baseline: 4.1478x; 1.6415x over previous
#include <cuda_runtime.h>
#include <math.h>

#define NN   512
#define FIN  256
#define HF   64
#define KTOP 12
#define LALPHA 0.2f
#define RMAX 16     // strict > kth(12th largest) gives <= 11 adjacency entries
#define UMAX 24     // union of adjacency columns and adjacency rows: <= 22
#define NEGINF -3.4e38f

// ---------------- scratch (__device__ globals; no allocation) ----------------
__device__ __align__(16) float g_A[NN * NN];            // V @ V^T
__device__ float g_cand[64 * KTOP];
__device__ float g_kth;
__device__ int   g_rowCnt[NN];
__device__ int   g_cols[NN][RMAX];
__device__ int   g_nRows;
__device__ int   g_rowIds[RMAX];
__device__ int   g_rIndexOf[NN];
__device__ int   g_nD;
__device__ int   g_dIndexOf[NN];
__device__ int   g_nU;
__device__ int   g_uList[UMAX];
__device__ int   g_uRowIdx[RMAX];
__device__ __align__(16) float g_w2[NN * FIN];
__device__ __align__(16) float g_e2[NN * NN];
__device__ __align__(16) float g_WhC[NN * UMAX * HF];
__device__ __align__(16) float g_midR[RMAX * NN * HF];
__device__ __align__(16) float g_part[256 * RMAX * HF];
__device__ float g_Wh2[RMAX * HF];
__device__ float g_e12[RMAX];
__device__ float g_e22[RMAX];

__device__ __forceinline__ float lrelu(float x) { return x > 0.f ? x : LALPHA * x; }
__device__ __forceinline__ float eluf(float x)  { return x > 0.f ? x : expm1f(x); }

// ---- 1) A = V @ V^T, tiled 64x64, fused per-block top-12 candidates ---------
__global__ void k_vvt_topk(const float* __restrict__ V) {
    __shared__ __align__(16) float sbuf[2 * 64 * 68];   // 34.8 KB
    float (*sViT)[68] = (float(*)[68])sbuf;             // [k][i]
    float (*sVjT)[68] = (float(*)[68])(sbuf + 64 * 68); // [k][j]
    int tid = threadIdx.x;                              // 256
    int bi = blockIdx.x >> 3, bj = blockIdx.x & 7;
    int i0 = bi * 64, j0 = bj * 64;
#pragma unroll
    for (int q = 0; q < 4; q++) {
        int idx = q * 1024 + tid * 4;
        int r = idx >> 6, k = idx & 63;
        float4 v = *(const float4*)(V + (size_t)(i0 + r) * HF + k);
        sViT[k][r] = v.x; sViT[k + 1][r] = v.y; sViT[k + 2][r] = v.z; sViT[k + 3][r] = v.w;
        float4 w = *(const float4*)(V + (size_t)(j0 + r) * HF + k);
        sVjT[k][r] = w.x; sVjT[k + 1][r] = w.y; sVjT[k + 2][r] = w.z; sVjT[k + 3][r] = w.w;
    }
    __syncthreads();
    int tx = tid & 15, ty = tid >> 4;
    float acc[4][4];
#pragma unroll
    for (int a = 0; a < 4; a++)
#pragma unroll
        for (int b = 0; b < 4; b++) acc[a][b] = 0.f;
#pragma unroll 8
    for (int k = 0; k < 64; k++) {
        float4 av = *(const float4*)&sViT[k][ty * 4];
        float4 bv = *(const float4*)&sVjT[k][tx * 4];
        acc[0][0] += av.x * bv.x; acc[0][1] += av.x * bv.y; acc[0][2] += av.x * bv.z; acc[0][3] += av.x * bv.w;
        acc[1][0] += av.y * bv.x; acc[1][1] += av.y * bv.y; acc[1][2] += av.y * bv.z; acc[1][3] += av.y * bv.w;
        acc[2][0] += av.z * bv.x; acc[2][1] += av.z * bv.y; acc[2][2] += av.z * bv.z; acc[2][3] += av.z * bv.w;
        acc[3][0] += av.w * bv.x; acc[3][1] += av.w * bv.y; acc[3][2] += av.w * bv.z; acc[3][3] += av.w * bv.w;
    }
#pragma unroll
    for (int a = 0; a < 4; a++)
        *(float4*)(g_A + (size_t)(i0 + ty * 4 + a) * NN + j0 + tx * 4) =
            make_float4(acc[a][0], acc[a][1], acc[a][2], acc[a][3]);
    // per-thread sorted top-12 over the 16 register outputs
    float loc[KTOP];
#pragma unroll
    for (int k = 0; k < KTOP; k++) loc[k] = NEGINF;
#pragma unroll
    for (int a = 0; a < 4; a++)
#pragma unroll
        for (int b = 0; b < 4; b++) {
            float v = acc[a][b];
            if (v > loc[0]) {
                loc[0] = v;
#pragma unroll
                for (int k = 0; k < KTOP - 1; k++)
                    if (loc[k] > loc[k + 1]) { float t = loc[k]; loc[k] = loc[k + 1]; loc[k + 1] = t; }
            }
        }
    __syncthreads();                                    // tiles dead; overlay
    float* s  = sbuf;                                   // 256*12
    float* rv = sbuf + 256 * KTOP;                      // 256
    int*   ri = (int*)(sbuf + 256 * KTOP + 256);        // 256
#pragma unroll
    for (int k = 0; k < KTOP; k++) s[tid * KTOP + k] = loc[k];
    __syncthreads();
    for (int round = 0; round < KTOP; round++) {
        float bv = NEGINF; int bi2 = 0;
#pragma unroll
        for (int k = 0; k < KTOP; k++) {
            float v = s[tid * KTOP + k];
            if (v > bv) { bv = v; bi2 = tid * KTOP + k; }
        }
        rv[tid] = bv; ri[tid] = bi2;
        __syncthreads();
        for (int st = 128; st > 0; st >>= 1) {
            if (tid < st && rv[tid + st] > rv[tid]) { rv[tid] = rv[tid + st]; ri[tid] = ri[tid + st]; }
            __syncthreads();
        }
        if (tid == 0) {
            g_cand[blockIdx.x * KTOP + round] = rv[0];
            s[ri[0]] = NEGINF;
        }
        __syncthreads();
    }
}

// ---------------- 2) merge candidates -> 12th largest ----------------
__global__ void k_topkB() {
    __shared__ float s[256 * KTOP];
    __shared__ float rv[256];
    __shared__ int   ri[256];
    int tid = threadIdx.x;
    float loc[KTOP];
#pragma unroll
    for (int k = 0; k < KTOP; k++) loc[k] = NEGINF;
    for (int idx = tid; idx < 64 * KTOP; idx += 256) {
        float v = g_cand[idx];
        if (v > loc[0]) {
            loc[0] = v;
#pragma unroll
            for (int k = 0; k < KTOP - 1; k++)
                if (loc[k] > loc[k + 1]) { float t = loc[k]; loc[k] = loc[k + 1]; loc[k + 1] = t; }
        }
    }
#pragma unroll
    for (int k = 0; k < KTOP; k++) s[tid * KTOP + k] = loc[k];
    __syncthreads();
    for (int round = 0; round < KTOP; round++) {
        float bv = NEGINF; int bi = 0;
#pragma unroll
        for (int k = 0; k < KTOP; k++) {
            float v = s[tid * KTOP + k];
            if (v > bv) { bv = v; bi = tid * KTOP + k; }
        }
        rv[tid] = bv; ri[tid] = bi;
        __syncthreads();
        for (int st = 128; st > 0; st >>= 1) {
            if (tid < st && rv[tid + st] > rv[tid]) { rv[tid] = rv[tid + st]; ri[tid] = ri[tid + st]; }
            __syncthreads();
        }
        if (round == KTOP - 1) {
            if (tid == 0) g_kth = rv[0];
        } else {
            if (tid == 0) s[ri[0]] = NEGINF;
            __syncthreads();
        }
    }
}

// ------- 3) warp-per-row adjacency scan: prefetch 16 (MLP=16) then ballot ----
__global__ void k_rowscan(float* __restrict__ adj, int hasAdj) {
    int warp = threadIdx.x >> 5, lane = threadIdx.x & 31;
    int i = blockIdx.x * 8 + warp;
    float kth = g_kth;
    float v[16];
#pragma unroll
    for (int t = 0; t < 16; t++) v[t] = g_A[i * NN + t * 32 + lane];
    int cnt = 0;
#pragma unroll
    for (int t = 0; t < 16; t++) {
        bool p = v[t] > kth;
        if (hasAdj) adj[i * NN + t * 32 + lane] = p ? 1.f : 0.f;
        unsigned mask = __ballot_sync(0xffffffffu, p);
        if (p) {
            int pos = cnt + __popc(mask & ((1u << lane) - 1u));
            if (pos < RMAX) g_cols[i][pos] = t * 32 + lane;
        }
        cnt += __popc(mask);
    }
    if (lane == 0) g_rowCnt[i] = cnt < RMAX ? cnt : RMAX;
    int gt = blockIdx.x * 256 + threadIdx.x;
    if (gt < NN) { g_rIndexOf[gt] = -1; g_dIndexOf[gt] = -1; }
}

// -------- 4) build index structures (ballot-assisted serial tail) ------------
__global__ void k_rows2() {
    __shared__ int sCnt[NN];
    __shared__ int sCols[NN][RMAX];
    __shared__ int sD[NN];
    __shared__ unsigned sMask[16];
    int tid = threadIdx.x;                          // 512 threads
    int cnt = g_rowCnt[tid];
    sCnt[tid] = cnt;
    sD[tid] = -1;
#pragma unroll
    for (int k = 0; k < RMAX; k++) sCols[tid][k] = g_cols[tid][k];
    unsigned wm = __ballot_sync(0xffffffffu, cnt > 0);
    if ((tid & 31) == 0) sMask[tid >> 5] = wm;
    __syncthreads();
    if (tid == 0) {
        int rowIds[RMAX];
        int nR = 0;
        for (int w = 0; w < 16; w++) {
            unsigned m = sMask[w];
            while (m && nR < RMAX) {
                int b = __ffs(m) - 1; m &= m - 1;
                int r = w * 32 + b;
                g_rIndexOf[r] = nR; g_rowIds[nR] = r; rowIds[nR] = r; nR++;
            }
        }
        g_nRows = nR;
        int nD = 0;
        for (int rr = 0; rr < nR; rr++) {
            int row = rowIds[rr];
            int c = sCnt[row];
            for (int k = 0; k < c; k++) {
                int j = sCols[row][k];
                if (sD[j] < 0 && nD < UMAX) {
                    sD[j] = nD; g_dIndexOf[j] = nD; g_uList[nD] = j; nD++;
                }
            }
        }
        g_nD = nD;
        int nU = nD;
        for (int rr = 0; rr < nR; rr++) {
            int i = rowIds[rr];
            if (sD[i] >= 0) g_uRowIdx[rr] = sD[i];
            else if (nU < UMAX) { g_uRowIdx[rr] = nU; g_uList[nU] = i; sD[i] = nU; nU++; }
        }
        g_nU = nU;
        for (int u = nU; u < UMAX; u++) g_uList[u] = 0;
    }
}

// ---- 5) one pass over W_stack, shared-staged tiles: WhC + w2, no shuffles ---
#define WS_SW   (64 * 65)                 // sW[64][65]
#define WS_SXD  (WS_SW)                   // sXd[UMAX][FIN]
#define WS_SP   (WS_SW + UMAX * FIN)      // sp[64][4]
#define WS_SA2  (WS_SP + 256)             // sa2[64]
#define WS_TOT  (WS_SA2 + HF)             // 10688 floats = 42.75 KB

template<int U>
__device__ __forceinline__ void wstack_body(float* sbuf, const float* __restrict__ X,
        const float* __restrict__ W, const float* __restrict__ a, int h, int tid, int nU) {
    float (*sW)[65] = (float(*)[65])sbuf;
    float* sXd = sbuf + WS_SXD;
    float (*sp)[4] = (float(*)[4])(sbuf + WS_SP);
    float* sa2 = sbuf + WS_SA2;
    if (tid < HF) sa2[tid] = a[h * 2 * HF + HF + tid];
    for (int idx = tid; idx < U * FIN; idx += 256) {
        int u = idx >> 8, f = idx & 255;
        sXd[u * FIN + f] = (u < nU) ? X[g_uList[u] * FIN + f] : 0.f;
    }
    int fg = tid >> 6, c = tid & 63;
    float acc[U];
#pragma unroll
    for (int u = 0; u < U; u++) acc[u] = 0.f;
    const float* Wh = W + (size_t)h * FIN * HF;
    for (int t = 0; t < 4; t++) {
        const float* tileBase = Wh + t * 64 * HF;
#pragma unroll
        for (int q = 0; q < 4; q++) {
            int idx = q * 1024 + tid * 4;
            float4 v = *(const float4*)(tileBase + idx);
            int r = idx >> 6, k = idx & 63;
            sW[r][k] = v.x; sW[r][k + 1] = v.y; sW[r][k + 2] = v.z; sW[r][k + 3] = v.w;
        }
        __syncthreads();                 // covers sXd/sa2 population on t==0
        int fbase = t * 64 + fg * 16;
#pragma unroll
        for (int k = 0; k < 16; k++) {
            float wv = sW[fg * 16 + k][c];
#pragma unroll
            for (int u = 0; u < U; u++) acc[u] += sXd[u * FIN + fbase + k] * wv;
        }
        int fl = tid >> 2, q2 = tid & 3;
        float s = 0.f;
#pragma unroll
        for (int cc = q2 * 16; cc < q2 * 16 + 16; cc++) s += sW[fl][cc] * sa2[cc];
        sp[fl][q2] = s;
        __syncthreads();
        if (tid < 64)
            g_w2[h * FIN + t * 64 + tid] = sp[tid][0] + sp[tid][1] + sp[tid][2] + sp[tid][3];
        __syncthreads();                 // before next tile overwrites sW/sp
    }
    float (*sRed)[HF + 1] = (float(*)[HF + 1])sbuf;    // [4*U][65], overlays
#pragma unroll
    for (int u = 0; u < U; u++) sRed[fg * U + u][c] = acc[u];
    __syncthreads();
    if (fg == 0)
#pragma unroll
        for (int u = 0; u < U; u++)
            g_WhC[(h * UMAX + u) * HF + c] =
                sRed[0 * U + u][c] + sRed[1 * U + u][c] + sRed[2 * U + u][c] + sRed[3 * U + u][c];
}

__global__ void k_wstack(const float* __restrict__ X, const float* __restrict__ W,
                         const float* __restrict__ a) {
    __shared__ __align__(16) float sbuf[WS_TOT];
    int h = blockIdx.x, tid = threadIdx.x;   // 256 threads
    int nU = g_nU;
    if (nU <= 12)      wstack_body<12>(sbuf, X, W, a, h, tid, nU);
    else if (nU <= 16) wstack_body<16>(sbuf, X, W, a, h, tid, nU);
    else               wstack_body<UMAX>(sbuf, X, W, a, h, tid, nU);
}

// ------- 6) E2 = w2 @ X^T  (register-tiled 64x32, 4x2 per thread) ------------
__global__ void k_e2(const float* __restrict__ X) {
    __shared__ __align__(16) float sA[32][68];   // X:  [k][j]
    __shared__ __align__(16) float sB[32][34];   // w2: [k][h]
    int tid = threadIdx.x;                       // 256
    int j0 = blockIdx.x * 64, h0 = blockIdx.y * 32;
    int tx = tid & 15, ty = tid >> 4;
    float acc[4][2];
#pragma unroll
    for (int i = 0; i < 4; i++) { acc[i][0] = 0.f; acc[i][1] = 0.f; }
    for (int kt = 0; kt < FIN / 32; kt++) {
        int k0 = kt * 32;
#pragma unroll
        for (int l = 0; l < 2; l++) {
            int idx = tid + l * 256;
            int row = idx >> 3, q = idx & 7;
            float4 v = *(const float4*)(X + (size_t)(j0 + row) * FIN + k0 + q * 4);
            sA[q * 4 + 0][row] = v.x; sA[q * 4 + 1][row] = v.y;
            sA[q * 4 + 2][row] = v.z; sA[q * 4 + 3][row] = v.w;
        }
        {
            int row = tid >> 3, q = tid & 7;
            float4 v = *(const float4*)(g_w2 + (size_t)(h0 + row) * FIN + k0 + q * 4);
            sB[q * 4 + 0][row] = v.x; sB[q * 4 + 1][row] = v.y;
            sB[q * 4 + 2][row] = v.z; sB[q * 4 + 3][row] = v.w;
        }
        __syncthreads();
#pragma unroll
        for (int k = 0; k < 32; k++) {
            float4 av = *(const float4*)&sA[k][tx * 4];
            float b0 = sB[k][ty * 2], b1 = sB[k][ty * 2 + 1];
            acc[0][0] += av.x * b0; acc[1][0] += av.y * b0;
            acc[2][0] += av.z * b0; acc[3][0] += av.w * b0;
            acc[0][1] += av.x * b1; acc[1][1] += av.y * b1;
            acc[2][1] += av.z * b1; acc[3][1] += av.w * b1;
        }
        __syncthreads();
    }
#pragma unroll
    for (int b = 0; b < 2; b++)
#pragma unroll
        for (int i = 0; i < 4; i++)
            g_e2[(size_t)(h0 + ty * 2 + b) * NN + j0 + tx * 4 + i] = acc[i][b];
}

// --- 7) block-per-head: block max (lrelu monotone), single exp pass ----------
__global__ void k_heads(const float* __restrict__ a_stack) {
    __shared__ float se2[NN];
    __shared__ float sred[256];
    int h = blockIdx.x, tid = threadIdx.x;       // 512 threads
    se2[tid] = g_e2[(size_t)h * NN + tid];
    __syncthreads();
    if (tid < 256) sred[tid] = fmaxf(se2[tid], se2[tid + 256]);
    __syncthreads();
    for (int st = 128; st > 0; st >>= 1) {
        if (tid < st) sred[tid] = fmaxf(sred[tid], sred[tid + st]);
        __syncthreads();
    }
    float bmax = sred[0];
    int warp = tid >> 5, lane = tid & 31;
    int nR = g_nRows;
    if (warp >= nR) return;
    int slot = warp;
    int i = g_rowIds[slot];
    int ui = g_uRowIdx[slot];
    const float* whU = g_WhC + (h * UMAX + ui) * HF;
    const float* a1  = a_stack + (size_t)h * 2 * HF;
    float p = whU[lane] * a1[lane] + whU[lane + 32] * a1[lane + 32];
#pragma unroll
    for (int o = 16; o > 0; o >>= 1) p += __shfl_xor_sync(0xffffffffu, p, o);
    float e1 = p;
    float m = lrelu(e1 + bmax);                  // exact max: lrelu is monotone
    float s = 0.f;
#pragma unroll
    for (int t = 0; t < 16; t++)
        s += __expf(lrelu(e1 + se2[t * 32 + lane]) - m);
#pragma unroll
    for (int o = 16; o > 0; o >>= 1) s += __shfl_xor_sync(0xffffffffu, s, o);
    int cnt = g_rowCnt[i];
    float coef = 0.f; int jd = 0;
    if (lane < cnt) {
        int j = g_cols[i][lane];
        jd = g_dIndexOf[j];
        coef = __expf(lrelu(e1 + se2[j]) - m) / s;
    }
    float acc0 = 0.f, acc1 = 0.f;
    for (int k = 0; k < cnt; k++) {
        float cf  = __shfl_sync(0xffffffffu, coef, k);
        int   jdk = __shfl_sync(0xffffffffu, jd, k);
        const float* whc = g_WhC + (h * UMAX + jdk) * HF;
        acc0 += cf * whc[lane];
        acc1 += cf * whc[lane + 32];
    }
    float* dst = g_midR + (size_t)slot * (NN * HF) + h * HF;
    dst[lane]      = eluf(acc0);
    dst[lane + 32] = eluf(acc1);
}

// -------- 8) Wh2 = midR @ W_out (split-K partials; W_out read once) ----------
__global__ void k_wh2(const float* __restrict__ Wout) {
    __shared__ float smid[RMAX][512];   // 32 KB
    int kb = blockIdx.x, tid = threadIdx.x;
    int nR = g_nRows;
    int k0 = kb * 512;
    for (int idx = tid; idx < RMAX * 512; idx += 256) {
        int r = idx / 512, k = idx % 512;
        smid[r][k] = (r < nR) ? g_midR[(size_t)r * (NN * HF) + k0 + k] : 0.f;
    }
    __syncthreads();
    int c = tid & 63, kg = tid >> 6;
    float acc[RMAX];
#pragma unroll
    for (int r = 0; r < RMAX; r++) acc[r] = 0.f;
    for (int kk = kg * 128; kk < kg * 128 + 128; kk++) {
        float wv = Wout[(size_t)(k0 + kk) * HF + c];
#pragma unroll
        for (int r = 0; r < RMAX; r++) acc[r] += smid[r][kk] * wv;
    }
    int pp = kb * 4 + kg;
#pragma unroll
    for (int r = 0; r < RMAX; r++) g_part[(pp * RMAX + r) * HF + c] = acc[r];
}

// -------- 9) reduce partials (16 blocks); e1_2 / e2_2 ----------
__global__ void k_wh2red(const float* __restrict__ aout) {
    __shared__ float sW[HF];
    int r = blockIdx.x, c = threadIdx.x;
    float acc = 0.f;
#pragma unroll 8
    for (int pp = 0; pp < 256; pp++) acc += g_part[(pp * RMAX + r) * HF + c];
    g_Wh2[r * HF + c] = acc;
    sW[c] = acc;
    __syncthreads();
    if (c < 2) {
        const float* av = aout + c * HF;
        float e = 0.f;
        for (int cc = 0; cc < HF; cc++) e += sW[cc] * av[cc];
        if (c == 0) g_e12[r] = e; else g_e22[r] = e;
    }
}

// -------- 10) second-layer softmax (closed-form denominator) + final elu -----
__global__ void k_final(const float* __restrict__ V, float* __restrict__ out) {
    __shared__ float sMD[2];
    int i = blockIdx.x, c = threadIdx.x;
    int r = g_rIndexOf[i];
    float val = 0.f;
    if (r >= 0) {
        if (c == 0) {
            int nR = g_nRows;
            float e1 = g_e12[r];
            float base = lrelu(e1);
            float m = base;
            for (int rr = 0; rr < nR; rr++) m = fmaxf(m, lrelu(e1 + g_e22[rr]));
            float den = (float)(NN - nR) * __expf(base - m);
            for (int rr = 0; rr < nR; rr++) den += __expf(lrelu(e1 + g_e22[rr]) - m);
            sMD[0] = m; sMD[1] = den;
        }
        __syncthreads();
        float m = sMD[0], den = sMD[1];
        float e1 = g_e12[r];
        float acc = 0.f;
        int cnt = g_rowCnt[i];
        for (int k = 0; k < cnt; k++) {
            int j  = g_cols[i][k];
            int rj = g_rIndexOf[j];
            if (rj >= 0) {
                float coef = __expf(lrelu(e1 + g_e22[rj]) - m) / den;
                acc += coef * g_Wh2[rj * HF + c];
            }
        }
        val = eluf(V[i * HF + c] * eluf(acc));
    }
    out[i * HF + c] = val;
}

// ---------------- launcher ----------------
extern "C" void kernel_launch(void* const* d_in, const int* in_sizes, int n_in,
                              void* d_out, int out_size) {
    const float* X    = (const float*)d_in[0];
    const float* Wst  = (const float*)d_in[1];
    const float* ast  = (const float*)d_in[2];
    const float* Wout = (const float*)d_in[3];
    const float* aout = (const float*)d_in[4];
    const float* V    = (const float*)d_in[5];

    float* base = (float*)d_out;
    float* adjP = nullptr;
    float* finP = nullptr;
    if (out_size >= NN * NN + NN * HF)      { adjP = base; finP = base + NN * NN; }
    else if (out_size == NN * HF)           { finP = base; }
    else if (out_size == NN * NN)           { adjP = base; }
    else                                    { finP = base; }

    k_vvt_topk<<<64, 256>>>(V);
    k_topkB<<<1, 256>>>();
    k_rowscan<<<64, 256>>>(adjP, adjP != nullptr);
    k_rows2<<<1, NN>>>();
    k_wstack<<<NN, 256>>>(X, Wst, ast);
    k_e2<<<dim3(8, 16), 256>>>(X);
    k_heads<<<NN, NN>>>(ast);
    k_wh2<<<64, 256>>>(Wout);
    k_wh2red<<<RMAX, HF>>>(aout);
    if (finP) k_final<<<NN, HF>>>(V, finP);
}

// round 6
// speedup vs baseline: 4.1512x; 1.0008x over previous
#include <cuda_runtime.h>
#include <math.h>

#define NN   512
#define FIN  256
#define HF   64
#define KTOP 12
#define LALPHA 0.2f
#define RMAX 16     // strict > kth(12th largest) gives <= 11 adjacency entries
#define UMAX 24     // union of adjacency columns and adjacency rows: <= 22
#define NEGINF -3.4e38f

// ---------------- scratch (__device__ globals; no allocation) ----------------
__device__ __align__(16) float g_A[NN * NN];            // V @ V^T
__device__ float g_cand[64 * KTOP];
__device__ float g_kth;
__device__ int   g_rowCnt[NN];
__device__ int   g_cols[NN][RMAX];
__device__ int   g_nRows;
__device__ int   g_rowIds[RMAX];
__device__ int   g_rIndexOf[NN];
__device__ int   g_nD;
__device__ int   g_dIndexOf[NN];
__device__ int   g_nU;
__device__ int   g_uList[UMAX];
__device__ int   g_uRowIdx[RMAX];
__device__ __align__(16) float g_w2[NN * FIN];
__device__ __align__(16) float g_e2[NN * NN];
__device__ __align__(16) float g_WhC[NN * UMAX * HF];
__device__ __align__(16) float g_midR[RMAX * NN * HF];
__device__ __align__(16) float g_part[256 * RMAX * HF];
__device__ float g_Wh2[RMAX * HF];
__device__ float g_e12[RMAX];
__device__ float g_e22[RMAX];

__device__ __forceinline__ float lrelu(float x) { return x > 0.f ? x : LALPHA * x; }
__device__ __forceinline__ float eluf(float x)  { return x > 0.f ? x : expm1f(x); }

// ---- 1) A = V @ V^T, tiled 64x64, fused per-block top-12 candidates ---------
__global__ void k_vvt_topk(const float* __restrict__ V) {
    __shared__ __align__(16) float sbuf[2 * 64 * 68];   // 34.8 KB
    float (*sViT)[68] = (float(*)[68])sbuf;             // [k][i]
    float (*sVjT)[68] = (float(*)[68])(sbuf + 64 * 68); // [k][j]
    int tid = threadIdx.x;                              // 256
    int bi = blockIdx.x >> 3, bj = blockIdx.x & 7;
    int i0 = bi * 64, j0 = bj * 64;
#pragma unroll
    for (int q = 0; q < 4; q++) {
        int idx = q * 1024 + tid * 4;
        int r = idx >> 6, k = idx & 63;
        float4 v = *(const float4*)(V + (size_t)(i0 + r) * HF + k);
        sViT[k][r] = v.x; sViT[k + 1][r] = v.y; sViT[k + 2][r] = v.z; sViT[k + 3][r] = v.w;
        float4 w = *(const float4*)(V + (size_t)(j0 + r) * HF + k);
        sVjT[k][r] = w.x; sVjT[k + 1][r] = w.y; sVjT[k + 2][r] = w.z; sVjT[k + 3][r] = w.w;
    }
    __syncthreads();
    int tx = tid & 15, ty = tid >> 4;
    float acc[4][4];
#pragma unroll
    for (int a = 0; a < 4; a++)
#pragma unroll
        for (int b = 0; b < 4; b++) acc[a][b] = 0.f;
#pragma unroll 8
    for (int k = 0; k < 64; k++) {
        float4 av = *(const float4*)&sViT[k][ty * 4];
        float4 bv = *(const float4*)&sVjT[k][tx * 4];
        acc[0][0] += av.x * bv.x; acc[0][1] += av.x * bv.y; acc[0][2] += av.x * bv.z; acc[0][3] += av.x * bv.w;
        acc[1][0] += av.y * bv.x; acc[1][1] += av.y * bv.y; acc[1][2] += av.y * bv.z; acc[1][3] += av.y * bv.w;
        acc[2][0] += av.z * bv.x; acc[2][1] += av.z * bv.y; acc[2][2] += av.z * bv.z; acc[2][3] += av.z * bv.w;
        acc[3][0] += av.w * bv.x; acc[3][1] += av.w * bv.y; acc[3][2] += av.w * bv.z; acc[3][3] += av.w * bv.w;
    }
#pragma unroll
    for (int a = 0; a < 4; a++)
        *(float4*)(g_A + (size_t)(i0 + ty * 4 + a) * NN + j0 + tx * 4) =
            make_float4(acc[a][0], acc[a][1], acc[a][2], acc[a][3]);
    // per-thread sorted top-12 over the 16 register outputs
    float loc[KTOP];
#pragma unroll
    for (int k = 0; k < KTOP; k++) loc[k] = NEGINF;
#pragma unroll
    for (int a = 0; a < 4; a++)
#pragma unroll
        for (int b = 0; b < 4; b++) {
            float v = acc[a][b];
            if (v > loc[0]) {
                loc[0] = v;
#pragma unroll
                for (int k = 0; k < KTOP - 1; k++)
                    if (loc[k] > loc[k + 1]) { float t = loc[k]; loc[k] = loc[k + 1]; loc[k + 1] = t; }
            }
        }
    __syncthreads();                                    // tiles dead; overlay
    float* s  = sbuf;                                   // 256*12
    float* rv = sbuf + 256 * KTOP;                      // 256
    int*   ri = (int*)(sbuf + 256 * KTOP + 256);        // 256
#pragma unroll
    for (int k = 0; k < KTOP; k++) s[tid * KTOP + k] = loc[k];
    __syncthreads();
    for (int round = 0; round < KTOP; round++) {
        float bv = NEGINF; int bi2 = 0;
#pragma unroll
        for (int k = 0; k < KTOP; k++) {
            float v = s[tid * KTOP + k];
            if (v > bv) { bv = v; bi2 = tid * KTOP + k; }
        }
        rv[tid] = bv; ri[tid] = bi2;
        __syncthreads();
        for (int st = 128; st > 0; st >>= 1) {
            if (tid < st && rv[tid + st] > rv[tid]) { rv[tid] = rv[tid + st]; ri[tid] = ri[tid + st]; }
            __syncthreads();
        }
        if (tid == 0) {
            g_cand[blockIdx.x * KTOP + round] = rv[0];
            s[ri[0]] = NEGINF;
        }
        __syncthreads();
    }
}

// ---------------- 2) merge candidates -> 12th largest ----------------
__global__ void k_topkB() {
    __shared__ float s[256 * KTOP];
    __shared__ float rv[256];
    __shared__ int   ri[256];
    int tid = threadIdx.x;
    float loc[KTOP];
#pragma unroll
    for (int k = 0; k < KTOP; k++) loc[k] = NEGINF;
    for (int idx = tid; idx < 64 * KTOP; idx += 256) {
        float v = g_cand[idx];
        if (v > loc[0]) {
            loc[0] = v;
#pragma unroll
            for (int k = 0; k < KTOP - 1; k++)
                if (loc[k] > loc[k + 1]) { float t = loc[k]; loc[k] = loc[k + 1]; loc[k + 1] = t; }
        }
    }
#pragma unroll
    for (int k = 0; k < KTOP; k++) s[tid * KTOP + k] = loc[k];
    __syncthreads();
    for (int round = 0; round < KTOP; round++) {
        float bv = NEGINF; int bi = 0;
#pragma unroll
        for (int k = 0; k < KTOP; k++) {
            float v = s[tid * KTOP + k];
            if (v > bv) { bv = v; bi = tid * KTOP + k; }
        }
        rv[tid] = bv; ri[tid] = bi;
        __syncthreads();
        for (int st = 128; st > 0; st >>= 1) {
            if (tid < st && rv[tid + st] > rv[tid]) { rv[tid] = rv[tid + st]; ri[tid] = ri[tid + st]; }
            __syncthreads();
        }
        if (round == KTOP - 1) {
            if (tid == 0) g_kth = rv[0];
        } else {
            if (tid == 0) s[ri[0]] = NEGINF;
            __syncthreads();
        }
    }
}

// ------- 3) warp-per-row adjacency scan: prefetch 16 (MLP=16) then ballot ----
__global__ void k_rowscan(float* __restrict__ adj, int hasAdj) {
    int warp = threadIdx.x >> 5, lane = threadIdx.x & 31;
    int i = blockIdx.x * 8 + warp;
    float kth = g_kth;
    float v[16];
#pragma unroll
    for (int t = 0; t < 16; t++) v[t] = g_A[i * NN + t * 32 + lane];
    int cnt = 0;
#pragma unroll
    for (int t = 0; t < 16; t++) {
        bool p = v[t] > kth;
        if (hasAdj) adj[i * NN + t * 32 + lane] = p ? 1.f : 0.f;
        unsigned mask = __ballot_sync(0xffffffffu, p);
        if (p) {
            int pos = cnt + __popc(mask & ((1u << lane) - 1u));
            if (pos < RMAX) g_cols[i][pos] = t * 32 + lane;
        }
        cnt += __popc(mask);
    }
    if (lane == 0) g_rowCnt[i] = cnt < RMAX ? cnt : RMAX;
    int gt = blockIdx.x * 256 + threadIdx.x;
    if (gt < NN) { g_rIndexOf[gt] = -1; g_dIndexOf[gt] = -1; }
}

// -------- 4) build index structures (ballot-assisted serial tail) ------------
__global__ void k_rows2() {
    __shared__ int sCnt[NN];
    __shared__ int sCols[NN][RMAX];
    __shared__ int sD[NN];
    __shared__ unsigned sMask[16];
    int tid = threadIdx.x;                          // 512 threads
    int cnt = g_rowCnt[tid];
    sCnt[tid] = cnt;
    sD[tid] = -1;
#pragma unroll
    for (int k = 0; k < RMAX; k++) sCols[tid][k] = g_cols[tid][k];
    unsigned wm = __ballot_sync(0xffffffffu, cnt > 0);
    if ((tid & 31) == 0) sMask[tid >> 5] = wm;
    __syncthreads();
    if (tid == 0) {
        int rowIds[RMAX];
        int nR = 0;
        for (int w = 0; w < 16; w++) {
            unsigned m = sMask[w];
            while (m && nR < RMAX) {
                int b = __ffs(m) - 1; m &= m - 1;
                int r = w * 32 + b;
                g_rIndexOf[r] = nR; g_rowIds[nR] = r; rowIds[nR] = r; nR++;
            }
        }
        g_nRows = nR;
        int nD = 0;
        for (int rr = 0; rr < nR; rr++) {
            int row = rowIds[rr];
            int c = sCnt[row];
            for (int k = 0; k < c; k++) {
                int j = sCols[row][k];
                if (sD[j] < 0 && nD < UMAX) {
                    sD[j] = nD; g_dIndexOf[j] = nD; g_uList[nD] = j; nD++;
                }
            }
        }
        g_nD = nD;
        int nU = nD;
        for (int rr = 0; rr < nR; rr++) {
            int i = rowIds[rr];
            if (sD[i] >= 0) g_uRowIdx[rr] = sD[i];
            else if (nU < UMAX) { g_uRowIdx[rr] = nU; g_uList[nU] = i; sD[i] = nU; nU++; }
        }
        g_nU = nU;
        for (int u = nU; u < UMAX; u++) g_uList[u] = 0;
    }
}

// ---- 5) one pass over W_stack, shared-staged tiles: WhC + w2, no shuffles ---
#define WS_SW   (64 * 65)                 // sW[64][65]
#define WS_SXD  (WS_SW)                   // sXd[UMAX][FIN]
#define WS_SP   (WS_SW + UMAX * FIN)      // sp[64][4]
#define WS_SA2  (WS_SP + 256)             // sa2[64]
#define WS_TOT  (WS_SA2 + HF)             // 10688 floats = 42.75 KB

template<int U>
__device__ __forceinline__ void wstack_body(float* sbuf, const float* __restrict__ X,
        const float* __restrict__ W, const float* __restrict__ a, int h, int tid, int nU) {
    float (*sW)[65] = (float(*)[65])sbuf;
    float* sXd = sbuf + WS_SXD;
    float (*sp)[4] = (float(*)[4])(sbuf + WS_SP);
    float* sa2 = sbuf + WS_SA2;
    if (tid < HF) sa2[tid] = a[h * 2 * HF + HF + tid];
    for (int idx = tid; idx < U * FIN; idx += 256) {
        int u = idx >> 8, f = idx & 255;
        sXd[u * FIN + f] = (u < nU) ? X[g_uList[u] * FIN + f] : 0.f;
    }
    int fg = tid >> 6, c = tid & 63;
    float acc[U];
#pragma unroll
    for (int u = 0; u < U; u++) acc[u] = 0.f;
    const float* Wh = W + (size_t)h * FIN * HF;
    for (int t = 0; t < 4; t++) {
        const float* tileBase = Wh + t * 64 * HF;
#pragma unroll
        for (int q = 0; q < 4; q++) {
            int idx = q * 1024 + tid * 4;
            float4 v = *(const float4*)(tileBase + idx);
            int r = idx >> 6, k = idx & 63;
            sW[r][k] = v.x; sW[r][k + 1] = v.y; sW[r][k + 2] = v.z; sW[r][k + 3] = v.w;
        }
        __syncthreads();                 // covers sXd/sa2 population on t==0
        int fbase = t * 64 + fg * 16;
#pragma unroll
        for (int k = 0; k < 16; k++) {
            float wv = sW[fg * 16 + k][c];
#pragma unroll
            for (int u = 0; u < U; u++) acc[u] += sXd[u * FIN + fbase + k] * wv;
        }
        int fl = tid >> 2, q2 = tid & 3;
        float s = 0.f;
#pragma unroll
        for (int cc = q2 * 16; cc < q2 * 16 + 16; cc++) s += sW[fl][cc] * sa2[cc];
        sp[fl][q2] = s;
        __syncthreads();
        if (tid < 64)
            g_w2[h * FIN + t * 64 + tid] = sp[tid][0] + sp[tid][1] + sp[tid][2] + sp[tid][3];
        __syncthreads();                 // before next tile overwrites sW/sp
    }
    float (*sRed)[HF + 1] = (float(*)[HF + 1])sbuf;    // [4*U][65], overlays
#pragma unroll
    for (int u = 0; u < U; u++) sRed[fg * U + u][c] = acc[u];
    __syncthreads();
    if (fg == 0)
#pragma unroll
        for (int u = 0; u < U; u++)
            g_WhC[(h * UMAX + u) * HF + c] =
                sRed[0 * U + u][c] + sRed[1 * U + u][c] + sRed[2 * U + u][c] + sRed[3 * U + u][c];
}

__global__ void k_wstack(const float* __restrict__ X, const float* __restrict__ W,
                         const float* __restrict__ a) {
    __shared__ __align__(16) float sbuf[WS_TOT];
    int h = blockIdx.x, tid = threadIdx.x;   // 256 threads
    int nU = g_nU;
    if (nU <= 12)      wstack_body<12>(sbuf, X, W, a, h, tid, nU);
    else if (nU <= 16) wstack_body<16>(sbuf, X, W, a, h, tid, nU);
    else               wstack_body<UMAX>(sbuf, X, W, a, h, tid, nU);
}

// ------- 6) E2 = w2 @ X^T  (register-tiled 64x32, 4x2 per thread) ------------
__global__ void k_e2(const float* __restrict__ X) {
    __shared__ __align__(16) float sA[32][68];   // X:  [k][j]
    __shared__ __align__(16) float sB[32][34];   // w2: [k][h]
    int tid = threadIdx.x;                       // 256
    int j0 = blockIdx.x * 64, h0 = blockIdx.y * 32;
    int tx = tid & 15, ty = tid >> 4;
    float acc[4][2];
#pragma unroll
    for (int i = 0; i < 4; i++) { acc[i][0] = 0.f; acc[i][1] = 0.f; }
    for (int kt = 0; kt < FIN / 32; kt++) {
        int k0 = kt * 32;
#pragma unroll
        for (int l = 0; l < 2; l++) {
            int idx = tid + l * 256;
            int row = idx >> 3, q = idx & 7;
            float4 v = *(const float4*)(X + (size_t)(j0 + row) * FIN + k0 + q * 4);
            sA[q * 4 + 0][row] = v.x; sA[q * 4 + 1][row] = v.y;
            sA[q * 4 + 2][row] = v.z; sA[q * 4 + 3][row] = v.w;
        }
        {
            int row = tid >> 3, q = tid & 7;
            float4 v = *(const float4*)(g_w2 + (size_t)(h0 + row) * FIN + k0 + q * 4);
            sB[q * 4 + 0][row] = v.x; sB[q * 4 + 1][row] = v.y;
            sB[q * 4 + 2][row] = v.z; sB[q * 4 + 3][row] = v.w;
        }
        __syncthreads();
#pragma unroll
        for (int k = 0; k < 32; k++) {
            float4 av = *(const float4*)&sA[k][tx * 4];
            float b0 = sB[k][ty * 2], b1 = sB[k][ty * 2 + 1];
            acc[0][0] += av.x * b0; acc[1][0] += av.y * b0;
            acc[2][0] += av.z * b0; acc[3][0] += av.w * b0;
            acc[0][1] += av.x * b1; acc[1][1] += av.y * b1;
            acc[2][1] += av.z * b1; acc[3][1] += av.w * b1;
        }
        __syncthreads();
    }
#pragma unroll
    for (int b = 0; b < 2; b++)
#pragma unroll
        for (int i = 0; i < 4; i++)
            g_e2[(size_t)(h0 + ty * 2 + b) * NN + j0 + tx * 4 + i] = acc[i][b];
}

// --- 7) block-per-head: block max (lrelu monotone), single exp pass ----------
__global__ void k_heads(const float* __restrict__ a_stack) {
    __shared__ float se2[NN];
    __shared__ float sred[256];
    int h = blockIdx.x, tid = threadIdx.x;       // 512 threads
    se2[tid] = g_e2[(size_t)h * NN + tid];
    __syncthreads();
    if (tid < 256) sred[tid] = fmaxf(se2[tid], se2[tid + 256]);
    __syncthreads();
    for (int st = 128; st > 0; st >>= 1) {
        if (tid < st) sred[tid] = fmaxf(sred[tid], sred[tid + st]);
        __syncthreads();
    }
    float bmax = sred[0];
    int warp = tid >> 5, lane = tid & 31;
    int nR = g_nRows;
    if (warp >= nR) return;
    int slot = warp;
    int i = g_rowIds[slot];
    int ui = g_uRowIdx[slot];
    const float* whU = g_WhC + (h * UMAX + ui) * HF;
    const float* a1  = a_stack + (size_t)h * 2 * HF;
    float p = whU[lane] * a1[lane] + whU[lane + 32] * a1[lane + 32];
#pragma unroll
    for (int o = 16; o > 0; o >>= 1) p += __shfl_xor_sync(0xffffffffu, p, o);
    float e1 = p;
    float m = lrelu(e1 + bmax);                  // exact max: lrelu is monotone
    float s = 0.f;
#pragma unroll
    for (int t = 0; t < 16; t++)
        s += __expf(lrelu(e1 + se2[t * 32 + lane]) - m);
#pragma unroll
    for (int o = 16; o > 0; o >>= 1) s += __shfl_xor_sync(0xffffffffu, s, o);
    int cnt = g_rowCnt[i];
    float coef = 0.f; int jd = 0;
    if (lane < cnt) {
        int j = g_cols[i][lane];
        jd = g_dIndexOf[j];
        coef = __expf(lrelu(e1 + se2[j]) - m) / s;
    }
    float acc0 = 0.f, acc1 = 0.f;
    for (int k = 0; k < cnt; k++) {
        float cf  = __shfl_sync(0xffffffffu, coef, k);
        int   jdk = __shfl_sync(0xffffffffu, jd, k);
        const float* whc = g_WhC + (h * UMAX + jdk) * HF;
        acc0 += cf * whc[lane];
        acc1 += cf * whc[lane + 32];
    }
    float* dst = g_midR + (size_t)slot * (NN * HF) + h * HF;
    dst[lane]      = eluf(acc0);
    dst[lane + 32] = eluf(acc1);
}

// -------- 8) Wh2 = midR @ W_out (split-K partials; W_out read once) ----------
__global__ void k_wh2(const float* __restrict__ Wout) {
    __shared__ float smid[RMAX][512];   // 32 KB
    int kb = blockIdx.x, tid = threadIdx.x;
    int nR = g_nRows;
    int k0 = kb * 512;
    for (int idx = tid; idx < RMAX * 512; idx += 256) {
        int r = idx / 512, k = idx % 512;
        smid[r][k] = (r < nR) ? g_midR[(size_t)r * (NN * HF) + k0 + k] : 0.f;
    }
    __syncthreads();
    int c = tid & 63, kg = tid >> 6;
    float acc[RMAX];
#pragma unroll
    for (int r = 0; r < RMAX; r++) acc[r] = 0.f;
    for (int kk = kg * 128; kk < kg * 128 + 128; kk++) {
        float wv = Wout[(size_t)(k0 + kk) * HF + c];
#pragma unroll
        for (int r = 0; r < RMAX; r++) acc[r] += smid[r][kk] * wv;
    }
    int pp = kb * 4 + kg;
#pragma unroll
    for (int r = 0; r < RMAX; r++) g_part[(pp * RMAX + r) * HF + c] = acc[r];
}

// -------- 9) reduce partials (16 blocks); e1_2 / e2_2 ----------
__global__ void k_wh2red(const float* __restrict__ aout) {
    __shared__ float sW[HF];
    int r = blockIdx.x, c = threadIdx.x;
    float acc = 0.f;
#pragma unroll 8
    for (int pp = 0; pp < 256; pp++) acc += g_part[(pp * RMAX + r) * HF + c];
    g_Wh2[r * HF + c] = acc;
    sW[c] = acc;
    __syncthreads();
    if (c < 2) {
        const float* av = aout + c * HF;
        float e = 0.f;
        for (int cc = 0; cc < HF; cc++) e += sW[cc] * av[cc];
        if (c == 0) g_e12[r] = e; else g_e22[r] = e;
    }
}

// -------- 10) second-layer softmax (closed-form denominator) + final elu -----
__global__ void k_final(const float* __restrict__ V, float* __restrict__ out) {
    __shared__ float sMD[2];
    int i = blockIdx.x, c = threadIdx.x;
    int r = g_rIndexOf[i];
    float val = 0.f;
    if (r >= 0) {
        if (c == 0) {
            int nR = g_nRows;
            float e1 = g_e12[r];
            float base = lrelu(e1);
            float m = base;
            for (int rr = 0; rr < nR; rr++) m = fmaxf(m, lrelu(e1 + g_e22[rr]));
            float den = (float)(NN - nR) * __expf(base - m);
            for (int rr = 0; rr < nR; rr++) den += __expf(lrelu(e1 + g_e22[rr]) - m);
            sMD[0] = m; sMD[1] = den;
        }
        __syncthreads();
        float m = sMD[0], den = sMD[1];
        float e1 = g_e12[r];
        float acc = 0.f;
        int cnt = g_rowCnt[i];
        for (int k = 0; k < cnt; k++) {
            int j  = g_cols[i][k];
            int rj = g_rIndexOf[j];
            if (rj >= 0) {
                float coef = __expf(lrelu(e1 + g_e22[rj]) - m) / den;
                acc += coef * g_Wh2[rj * HF + c];
            }
        }
        val = eluf(V[i * HF + c] * eluf(acc));
    }
    out[i * HF + c] = val;
}

// ---------------- launcher ----------------
extern "C" void kernel_launch(void* const* d_in, const int* in_sizes, int n_in,
                              void* d_out, int out_size) {
    const float* X    = (const float*)d_in[0];
    const float* Wst  = (const float*)d_in[1];
    const float* ast  = (const float*)d_in[2];
    const float* Wout = (const float*)d_in[3];
    const float* aout = (const float*)d_in[4];
    const float* V    = (const float*)d_in[5];

    float* base = (float*)d_out;
    float* adjP = nullptr;
    float* finP = nullptr;
    if (out_size >= NN * NN + NN * HF)      { adjP = base; finP = base + NN * NN; }
    else if (out_size == NN * HF)           { finP = base; }
    else if (out_size == NN * NN)           { adjP = base; }
    else                                    { finP = base; }

    k_vvt_topk<<<64, 256>>>(V);
    k_topkB<<<1, 256>>>();
    k_rowscan<<<64, 256>>>(adjP, adjP != nullptr);
    k_rows2<<<1, NN>>>();
    k_wstack<<<NN, 256>>>(X, Wst, ast);
    k_e2<<<dim3(8, 16), 256>>>(X);
    k_heads<<<NN, NN>>>(ast);
    k_wh2<<<64, 256>>>(Wout);
    k_wh2red<<<RMAX, HF>>>(aout);
    if (finP) k_final<<<NN, HF>>>(V, finP);
}